// round 9
// baseline (speedup 1.0000x reference)
#include <cuda_runtime.h>
#include <cuda_fp16.h>
#include <math.h>
#include <stdint.h>

// Problem constants (fixed by setup_inputs)
#define BB 8
#define NN 2000
#define HH 128
#define KK 32
#define MM (BB * NN)        // 16000 rows
#define KDIM 384            // concat [in_agg | out_agg | h]
#define KB 32               // k per pipeline stage (halfs)
#define NKB (KDIM / KB)     // 12 stages
#define ROWB 80             // padded smem row bytes (64 data + 16 pad)
#define STAGE_B (128 * ROWB)         // 10240 bytes per operand stage
#define SMEM_GEMM (4 * 2 * STAGE_B)  // 81920 bytes

#define NTILE 125           // 16000 / 128 exact
#define NGEMM (NTILE * 4)   // 500 (tile x dblock)
#define NTASKS (NTILE + NGEMM + NTILE + NGEMM)   // 1250
#define GRID_P 296          // 2 CTAs/SM on 148 SMs; all co-resident

// ---- scratch (device globals; no allocation allowed) ----------------------
__device__ __half g_Xh[MM * KDIM];             // X rows fp16, [m][k]
__device__ __half g_Wh[NKB * 4 * HH * KB];     // [kb][g][d][k] fp16
__device__ float  g_h[MM * HH];                // h after layer 1 (fp32)
__device__ float  g_c[MM * HH];                // cell scratch (fp32)
__device__ int    g_flag1[NTILE];              // agg1 tile done
__device__ int    g_flag2[NTILE];              // agg2 tile done
__device__ int    g_cnt1;                      // gemm1 tasks done

// ---- helpers ---------------------------------------------------------------
__device__ __forceinline__ uint32_t smem_u32(const void* p) {
    uint32_t a;
    asm("{ .reg .u64 t; cvta.to.shared.u64 t, %1; cvt.u32.u64 %0, t; }" : "=r"(a) : "l"(p));
    return a;
}

__device__ __forceinline__ void cp16(uint32_t s, const void* g) {
    asm volatile("cp.async.cg.shared.global [%0], [%1], 16;" :: "r"(s), "l"(g));
}

__device__ __forceinline__ void ldm_x4(uint32_t* r, uint32_t addr) {
    asm volatile("ldmatrix.sync.aligned.m8n8.x4.shared.b16 {%0,%1,%2,%3}, [%4];"
                 : "=r"(r[0]), "=r"(r[1]), "=r"(r[2]), "=r"(r[3]) : "r"(addr));
}

__device__ __forceinline__ void mma_f16(float* c, const uint32_t* a,
                                        uint32_t b0, uint32_t b1) {
    asm volatile(
        "mma.sync.aligned.m16n8k16.row.col.f32.f16.f16.f32 "
        "{%0,%1,%2,%3}, {%4,%5,%6,%7}, {%8,%9}, {%0,%1,%2,%3};"
        : "+f"(c[0]), "+f"(c[1]), "+f"(c[2]), "+f"(c[3])
        : "r"(a[0]), "r"(a[1]), "r"(a[2]), "r"(a[3]), "r"(b0), "r"(b1));
}

__device__ __forceinline__ float sigf(float x) { return 1.0f / (1.0f + expf(-x)); }

__device__ __forceinline__ int ld_acq(const int* p) {
    int v;
    asm volatile("ld.acquire.gpu.b32 %0, [%1];" : "=r"(v) : "l"(p) : "memory");
    return v;
}

#define WAITG(n) asm volatile("cp.async.wait_group %0;" :: "n"(n) : "memory")

// ---------------------------------------------------------------------------
// prep: g_Wh[kb][g][d][k] = half( A_g[d][kb*32+k] ); block 0 also resets flags.
// ---------------------------------------------------------------------------
__global__ void prep_kernel(const float* __restrict__ w_in,
                            const float* __restrict__ w_out,
                            const float* __restrict__ u_in,
                            const float* __restrict__ u_out) {
    int idx = blockIdx.x * blockDim.x + threadIdx.x;   // 196608 exact
    if (blockIdx.x == 0) {
        int t = threadIdx.x;
        if (t < NTILE) { g_flag1[t] = 0; g_flag2[t] = 0; }
        if (t == 255) g_cnt1 = 0;
    }
    int k = idx & 31;
    int d = (idx >> 5) & 127;
    int g = (idx >> 12) & 3;
    int kb = idx >> 14;
    int kg = kb * KB + k;
    float v;
    if (kg < 128) {
        v = w_in[(g * 128 + kg) * 128 + d];
    } else if (kg < 256) {
        v = w_out[(g * 128 + (kg - 128)) * 128 + d];
    } else {
        int kk = kg - 256;
        v = u_in[(g * 128 + kk) * 128 + d] + u_out[(g * 128 + kk) * 128 + d];
    }
    g_Wh[idx] = __float2half_rn(v);
}

// ---------------------------------------------------------------------------
// agg task: one tile = 128 nodes; 8 warps x 16 nodes. Uses smem for idx/mask
// broadcast. Writes X rows (fp16) of this tile only.
// ---------------------------------------------------------------------------
__device__ void do_agg(char* smem, int tile,
                       const float* __restrict__ h_src,
                       const int*   __restrict__ in_idx,
                       const float* __restrict__ in_msk,
                       const int*   __restrict__ out_idx,
                       const float* __restrict__ out_msk) {
    int tid = threadIdx.x;
    int wid = tid >> 5;
    int lane = tid & 31;

    // per-warp staging slice: 512B
    char* slice = smem + wid * 512;
    int*   si  = (int*)(slice);
    float* smi = (float*)(slice + 128);
    int*   so  = (int*)(slice + 256);
    float* smo = (float*)(slice + 384);

    const float4* h4 = (const float4*)h_src;

    for (int rep = 0; rep < 16; rep++) {
        int bn = tile * 128 + wid * 16 + rep;
        si [lane] = in_idx [bn * KK + lane];
        smi[lane] = in_msk [bn * KK + lane];
        so [lane] = out_idx[bn * KK + lane];
        smo[lane] = out_msk[bn * KK + lane];
        __syncwarp();

        int base_b = (bn / NN) * NN;
        float4 ai = make_float4(0.f, 0.f, 0.f, 0.f);
        float4 ao = make_float4(0.f, 0.f, 0.f, 0.f);

#pragma unroll 8
        for (int k = 0; k < KK; k++) {
            int   ji = si[k];
            float mi = smi[k];
            int   jo = so[k];
            float mo = smo[k];
            float4 vi = h4[(size_t)(base_b + ji) * 32 + lane];
            float4 vo = h4[(size_t)(base_b + jo) * 32 + lane];
            ai.x += mi * vi.x; ai.y += mi * vi.y; ai.z += mi * vi.z; ai.w += mi * vi.w;
            ao.x += mo * vo.x; ao.y += mo * vo.y; ao.z += mo * vo.z; ao.w += mo * vo.w;
        }

        __half2* X2 = (__half2*)(g_Xh + (size_t)bn * KDIM);
        X2[0 * 64 + lane * 2 + 0] = __floats2half2_rn(ai.x, ai.y);
        X2[0 * 64 + lane * 2 + 1] = __floats2half2_rn(ai.z, ai.w);
        X2[1 * 64 + lane * 2 + 0] = __floats2half2_rn(ao.x, ao.y);
        X2[1 * 64 + lane * 2 + 1] = __floats2half2_rn(ao.z, ao.w);
        float4 hv = h4[(size_t)bn * 32 + lane];
        X2[2 * 64 + lane * 2 + 0] = __floats2half2_rn(hv.x, hv.y);
        X2[2 * 64 + lane * 2 + 1] = __floats2half2_rn(hv.z, hv.w);
        __syncwarp();
    }
}

// ---------------------------------------------------------------------------
// gemm task: fp16 mma.sync GEMM + fused LSTM for (tile, dblock).
// Tile = 128 m x 32 d x 4 gates; 8 warps of 32m x 16d x 4g; 4-deep pipeline.
// ---------------------------------------------------------------------------
__device__ void do_gemm(char* smem, int tile, int dblock,
                        const float* __restrict__ bias,
                        const float* __restrict__ c_src,
                        float* __restrict__ c_dst,
                        float* __restrict__ h_dst) {
    uint32_t xs_u = smem_u32(smem);
    uint32_t ws_u = xs_u + 4 * STAGE_B;

    int tid = threadIdx.x;
    int wid = tid >> 5;
    int lane = tid & 31;
    int m_base = tile * 128;
    int d_base = dblock * 32;
    int m0 = (wid & 3) * 32;
    int d0 = (wid >> 2) * 16;

#define XS_ADDR(s, row, colh) (xs_u + (uint32_t)((s) * STAGE_B + (row) * ROWB + (colh) * 2))
#define WS_ADDR(s, row, colh) (ws_u + (uint32_t)((s) * STAGE_B + (row) * ROWB + (colh) * 2))

    int l_row = tid >> 1;
    int l_colh = (tid & 1) * 16;
    int wg = l_row >> 5;
    int wdl = l_row & 31;

    const __half* xg = g_Xh + (size_t)(m_base + l_row) * KDIM + l_colh;
    const __half* wg_p = g_Wh + ((size_t)(wg * HH) + d_base + wdl) * KB + l_colh;

#define LOAD_STAGE(kb)                                                          \
    {                                                                           \
        int s_ = (kb) & 3;                                                      \
        const __half* xp_ = xg + (size_t)(kb) * KB;                             \
        const __half* wp_ = wg_p + (size_t)(kb) * 4 * HH * KB;                  \
        cp16(XS_ADDR(s_, l_row, l_colh), xp_);                                  \
        cp16(XS_ADDR(s_, l_row, l_colh + 8), xp_ + 8);                          \
        cp16(WS_ADDR(s_, l_row, l_colh), wp_);                                  \
        cp16(WS_ADDR(s_, l_row, l_colh + 8), wp_ + 8);                          \
        asm volatile("cp.async.commit_group;" ::: "memory");                    \
    }

    float acc[4][2][2][4];
#pragma unroll
    for (int g = 0; g < 4; g++)
#pragma unroll
        for (int mt = 0; mt < 2; mt++)
#pragma unroll
            for (int dt = 0; dt < 2; dt++)
#pragma unroll
                for (int j = 0; j < 4; j++) acc[g][mt][dt][j] = 0.f;

    int frow = (lane & 7) + ((lane >> 3) & 1) * 8;
    int fcolh = (lane >> 4) * 8;

    LOAD_STAGE(0);
    LOAD_STAGE(1);
    LOAD_STAGE(2);

#pragma unroll
    for (int kb = 0; kb < NKB; kb++) {
        int s = kb & 3;
        if (kb + 3 < NKB) {
            LOAD_STAGE(kb + 3);
            WAITG(3);
        } else if (kb == NKB - 3) {
            WAITG(2);
        } else if (kb == NKB - 2) {
            WAITG(1);
        } else {
            WAITG(0);
        }
        __syncthreads();

#pragma unroll
        for (int ks = 0; ks < 2; ks++) {
            int colh = ks * 16 + fcolh;
            uint32_t a[2][4];
            ldm_x4(a[0], XS_ADDR(s, m0 + 0 + frow, colh));
            ldm_x4(a[1], XS_ADDR(s, m0 + 16 + frow, colh));
            uint32_t b[4][4];
#pragma unroll
            for (int g = 0; g < 4; g++)
                ldm_x4(b[g], WS_ADDR(s, g * 32 + d0 + frow, colh));
#pragma unroll
            for (int g = 0; g < 4; g++)
#pragma unroll
                for (int mt = 0; mt < 2; mt++)
#pragma unroll
                    for (int dt = 0; dt < 2; dt++)
                        mma_f16(acc[g][mt][dt], a[mt], b[g][dt], b[g][dt + 2]);
        }
        __syncthreads();
    }

    int gid = lane >> 2;
    int tig = lane & 3;

#pragma unroll
    for (int dt = 0; dt < 2; dt++) {
        int d = d_base + d0 + dt * 8 + tig * 2;
        float2 bi = *(const float2*)&bias[0 * HH + d];
        float2 bo = *(const float2*)&bias[1 * HH + d];
        float2 bf = *(const float2*)&bias[2 * HH + d];
        float2 bg = *(const float2*)&bias[3 * HH + d];
#pragma unroll
        for (int mt = 0; mt < 2; mt++) {
#pragma unroll
            for (int rr = 0; rr < 2; rr++) {
                int m = m_base + m0 + mt * 16 + gid + rr * 8;
                size_t off = (size_t)m * HH + d;
                float2 cv = *(const float2*)&c_src[off];

                float i0 = sigf(acc[0][mt][dt][rr * 2 + 0] + bi.x);
                float i1 = sigf(acc[0][mt][dt][rr * 2 + 1] + bi.y);
                float o0 = sigf(acc[1][mt][dt][rr * 2 + 0] + bo.x);
                float o1 = sigf(acc[1][mt][dt][rr * 2 + 1] + bo.y);
                float f0 = sigf(acc[2][mt][dt][rr * 2 + 0] + bf.x);
                float f1 = sigf(acc[2][mt][dt][rr * 2 + 1] + bf.y);
                float g0 = tanhf(acc[3][mt][dt][rr * 2 + 0] + bg.x);
                float g1 = tanhf(acc[3][mt][dt][rr * 2 + 1] + bg.y);

                float cn0 = f0 * cv.x + i0 * g0;
                float cn1 = f1 * cv.y + i1 * g1;
                *(float2*)&c_dst[off] = make_float2(cn0, cn1);
                *(float2*)&h_dst[off] = make_float2(o0 * tanhf(cn0), o1 * tanhf(cn1));
            }
        }
    }
#undef XS_ADDR
#undef WS_ADDR
#undef LOAD_STAGE
}

// ---------------------------------------------------------------------------
// Persistent worker: static task list with spin dependencies.
//   [0,125)      agg1 tile t          -> release g_flag1[t]
//   [125,625)    gemm1 (t = id%125, dblk = id/125), wait g_flag1[t]; count++
//   [625,750)    agg2 tile t, wait g_cnt1 == 500 -> release g_flag2[t]
//   [750,1250)   gemm2, wait g_flag2[t]
// ---------------------------------------------------------------------------
__global__ void __launch_bounds__(256, 2)
worker_kernel(const float* __restrict__ node_hidden,
              const float* __restrict__ cell,
              const float* __restrict__ bias,
              const float* __restrict__ in_msk,
              const float* __restrict__ out_msk,
              const int*   __restrict__ in_idx,
              const int*   __restrict__ out_idx,
              float* __restrict__ out) {
    extern __shared__ char smem[];
    int tid = threadIdx.x;

    for (int task = blockIdx.x; task < NTASKS; task += GRID_P) {
        if (task < NTILE) {
            int t = task;
            do_agg(smem, t, node_hidden, in_idx, in_msk, out_idx, out_msk);
            __syncthreads();
            __threadfence();
            if (tid == 0) atomicExch(&g_flag1[t], 1);
        } else if (task < NTILE + NGEMM) {
            int id = task - NTILE;
            int t = id % NTILE;
            int dblk = id / NTILE;
            if (tid == 0) {
                while (ld_acq(&g_flag1[t]) == 0) __nanosleep(200);
            }
            __syncthreads();
            __threadfence();
            do_gemm(smem, t, dblk, bias, cell, g_c, g_h);
            __syncthreads();
            __threadfence();
            if (tid == 0) atomicAdd(&g_cnt1, 1);
        } else if (task < NTILE + NGEMM + NTILE) {
            int t = task - (NTILE + NGEMM);
            if (tid == 0) {
                while (ld_acq(&g_cnt1) < NGEMM) __nanosleep(200);
            }
            __syncthreads();
            __threadfence();
            do_agg(smem, t, g_h, in_idx, in_msk, out_idx, out_msk);
            __syncthreads();
            __threadfence();
            if (tid == 0) atomicExch(&g_flag2[t], 1);
        } else {
            int id = task - (NTILE + NGEMM + NTILE);
            int t = id % NTILE;
            int dblk = id / NTILE;
            if (tid == 0) {
                while (ld_acq(&g_flag2[t]) == 0) __nanosleep(200);
            }
            __syncthreads();
            __threadfence();
            do_gemm(smem, t, dblk, bias, g_c, g_c, out);
        }
        __syncthreads();
    }
}

// ---------------------------------------------------------------------------
extern "C" void kernel_launch(void* const* d_in, const int* in_sizes, int n_in,
                              void* d_out, int out_size) {
    const float* node_hidden = (const float*)d_in[0];
    const float* cell        = (const float*)d_in[1];
    const float* w_in        = (const float*)d_in[2];
    const float* w_out       = (const float*)d_in[3];
    const float* u_in        = (const float*)d_in[4];
    const float* u_out       = (const float*)d_in[5];
    const float* b           = (const float*)d_in[6];
    const float* in_msk      = (const float*)d_in[7];
    const float* out_msk     = (const float*)d_in[8];
    const int*   in_idx      = (const int*)d_in[9];
    const int*   out_idx     = (const int*)d_in[10];
    float* out = (float*)d_out;

    cudaFuncSetAttribute(worker_kernel,
                         cudaFuncAttributeMaxDynamicSharedMemorySize, SMEM_GEMM);

    prep_kernel<<<(NKB * 4 * HH * KB) / 256, 256>>>(w_in, w_out, u_in, u_out);
    worker_kernel<<<GRID_P, 256, SMEM_GEMM>>>(node_hidden, cell, b, in_msk,
                                              out_msk, in_idx, out_idx, out);
}

// round 10
// speedup vs baseline: 1.2158x; 1.2158x over previous
#include <cuda_runtime.h>
#include <cuda_fp16.h>
#include <math.h>
#include <stdint.h>

// Problem constants (fixed by setup_inputs)
#define BB 8
#define NN 2000
#define HH 128
#define KK 32
#define MM (BB * NN)        // 16000 rows
#define KDIM 384            // concat [in_agg | out_agg | h]
#define KB 32               // k per pipeline stage (halfs)
#define NKB (KDIM / KB)     // 12 stages
#define ROWB 80             // padded smem row bytes (64 data + 16 pad)
#define STAGE_B (128 * ROWB)         // 10240 bytes per operand stage
#define SMEM_GEMM (4 * 2 * STAGE_B)  // 81920 bytes

#define NTILE 125           // 16000 / 128 exact
#define NTASK (NTILE * 4)   // 500 (tile x dblock) per layer
#define GRID_G 296          // 2 CTAs/SM x 148 SMs

// ---- scratch (device globals; no allocation allowed) ----------------------
__device__ __half g_Xh[MM * KDIM];             // X rows fp16, [m][k]
__device__ __half g_Wh[NKB * 4 * HH * KB];     // [kb][g][d][k] fp16
__device__ float  g_h[MM * HH];                // h after layer 1 (fp32)
__device__ float  g_c[MM * HH];                // cell scratch (fp32)
__device__ int    g_task[2];                   // work-steal counters per layer

// ---- helpers ---------------------------------------------------------------
__device__ __forceinline__ uint32_t smem_u32(const void* p) {
    uint32_t a;
    asm("{ .reg .u64 t; cvta.to.shared.u64 t, %1; cvt.u32.u64 %0, t; }" : "=r"(a) : "l"(p));
    return a;
}

__device__ __forceinline__ void cp16(uint32_t s, const void* g) {
    asm volatile("cp.async.cg.shared.global [%0], [%1], 16;" :: "r"(s), "l"(g));
}

__device__ __forceinline__ void ldm_x4(uint32_t* r, uint32_t addr) {
    asm volatile("ldmatrix.sync.aligned.m8n8.x4.shared.b16 {%0,%1,%2,%3}, [%4];"
                 : "=r"(r[0]), "=r"(r[1]), "=r"(r[2]), "=r"(r[3]) : "r"(addr));
}

__device__ __forceinline__ void mma_f16(float* c, const uint32_t* a,
                                        uint32_t b0, uint32_t b1) {
    asm volatile(
        "mma.sync.aligned.m16n8k16.row.col.f32.f16.f16.f32 "
        "{%0,%1,%2,%3}, {%4,%5,%6,%7}, {%8,%9}, {%0,%1,%2,%3};"
        : "+f"(c[0]), "+f"(c[1]), "+f"(c[2]), "+f"(c[3])
        : "r"(a[0]), "r"(a[1]), "r"(a[2]), "r"(a[3]), "r"(b0), "r"(b1));
}

__device__ __forceinline__ float sigf(float x) { return 1.0f / (1.0f + expf(-x)); }

#define WAITG(n) asm volatile("cp.async.wait_group %0;" :: "n"(n) : "memory")

// ---------------------------------------------------------------------------
// prep: g_Wh[kb][g][d][k] = half( A_g[d][kb*32+k] ); block 0 resets counters.
// ---------------------------------------------------------------------------
__global__ void prep_kernel(const float* __restrict__ w_in,
                            const float* __restrict__ w_out,
                            const float* __restrict__ u_in,
                            const float* __restrict__ u_out) {
    int idx = blockIdx.x * blockDim.x + threadIdx.x;   // 196608 exact
    if (blockIdx.x == 0 && threadIdx.x < 2) g_task[threadIdx.x] = 0;
    int k = idx & 31;
    int d = (idx >> 5) & 127;
    int g = (idx >> 12) & 3;
    int kb = idx >> 14;
    int kg = kb * KB + k;
    float v;
    if (kg < 128) {
        v = w_in[(g * 128 + kg) * 128 + d];
    } else if (kg < 256) {
        v = w_out[(g * 128 + (kg - 128)) * 128 + d];
    } else {
        int kk = kg - 256;
        v = u_in[(g * 128 + kk) * 128 + d] + u_out[(g * 128 + kk) * 128 + d];
    }
    g_Wh[idx] = __float2half_rn(v);
}

// ---------------------------------------------------------------------------
// Aggregation: TWO warps per node (one per edge set). 256 threads = 8 warps
// = 4 nodes. in-warp writes X seg0 + seg2 (h copy); out-warp writes seg1.
// ---------------------------------------------------------------------------
__global__ void agg_kernel(const float* __restrict__ h_ext, int use_ext,
                           const int*   __restrict__ in_idx,
                           const float* __restrict__ in_msk,
                           const int*   __restrict__ out_idx,
                           const float* __restrict__ out_msk) {
    const float* h_src = use_ext ? h_ext : g_h;
    __shared__ int   s_idx[8][KK];
    __shared__ float s_msk[8][KK];

    int tid = threadIdx.x;
    int wid = tid >> 5;
    int lane = tid & 31;
    int es = wid & 1;                 // 0 = in, 1 = out
    int bn = blockIdx.x * 4 + (wid >> 1);

    {
        const int*   ip = es ? out_idx : in_idx;
        const float* mp = es ? out_msk : in_msk;
        s_idx[wid][lane] = ip[bn * KK + lane];
        s_msk[wid][lane] = mp[bn * KK + lane];
    }
    __syncwarp();

    int base_b = (bn / NN) * NN;
    const float4* h4 = (const float4*)h_src;

    float4 a = make_float4(0.f, 0.f, 0.f, 0.f);

#pragma unroll 8
    for (int k = 0; k < KK; k++) {
        int   j = s_idx[wid][k];
        float m = s_msk[wid][k];
        float4 v = h4[(size_t)(base_b + j) * 32 + lane];
        a.x += m * v.x; a.y += m * v.y; a.z += m * v.z; a.w += m * v.w;
    }

    __half2* X2 = (__half2*)(g_Xh + (size_t)bn * KDIM);
    X2[es * 64 + lane * 2 + 0] = __floats2half2_rn(a.x, a.y);
    X2[es * 64 + lane * 2 + 1] = __floats2half2_rn(a.z, a.w);
    if (es == 0) {
        float4 hv = h4[(size_t)bn * 32 + lane];
        X2[2 * 64 + lane * 2 + 0] = __floats2half2_rn(hv.x, hv.y);
        X2[2 * 64 + lane * 2 + 1] = __floats2half2_rn(hv.z, hv.w);
    }
}

// ---------------------------------------------------------------------------
// fp16 mma.sync GEMM + fused LSTM. Persistent 296-CTA kernel, work-stealing
// (tile, dblock) tasks via atomic counter. CTA tile = 128m x 32d x 4 gates;
// 8 warps of 32m x 16d x 4g; 4-deep cp.async pipeline, 1 sync per k-iter.
// ---------------------------------------------------------------------------
__global__ void __launch_bounds__(256, 2)
gemm_lstm_mma(const float* __restrict__ bias,
              const float* __restrict__ c_ext,
              float* __restrict__ h_final,
              int layer) {
    const float* c_src = layer ? g_c : c_ext;
    float* c_dst = g_c;
    float* h_dst = layer ? h_final : g_h;

    extern __shared__ char smem[];
    uint32_t xs_u = smem_u32(smem);
    uint32_t ws_u = xs_u + 4 * STAGE_B;
    __shared__ int s_task;

    int tid = threadIdx.x;
    int wid = tid >> 5;
    int lane = tid & 31;
    int m0 = (wid & 3) * 32;
    int d0 = (wid >> 2) * 16;

#define XS_ADDR(s, row, colh) (xs_u + (uint32_t)((s) * STAGE_B + (row) * ROWB + (colh) * 2))
#define WS_ADDR(s, row, colh) (ws_u + (uint32_t)((s) * STAGE_B + (row) * ROWB + (colh) * 2))

    // loader lanes: row = tid>>1, base col = (tid&1)*16 halfs; 32B per operand
    int l_row = tid >> 1;
    int l_colh = (tid & 1) * 16;
    int wg = l_row >> 5;
    int wdl = l_row & 31;

    int frow = (lane & 7) + ((lane >> 3) & 1) * 8;
    int fcolh = (lane >> 4) * 8;
    int gid = lane >> 2;
    int tig = lane & 3;

    for (;;) {
        if (tid == 0) s_task = atomicAdd(&g_task[layer], 1);
        __syncthreads();
        int task = s_task;
        if (task >= NTASK) return;
        int tile = task >> 2;
        int dblock = task & 3;

        int m_base = tile * 128;
        int d_base = dblock * 32;

        const __half* xg = g_Xh + (size_t)(m_base + l_row) * KDIM + l_colh;
        const __half* wg_p = g_Wh + ((size_t)(wg * HH) + d_base + wdl) * KB + l_colh;

#define LOAD_STAGE(kb)                                                          \
        {                                                                       \
            int s_ = (kb) & 3;                                                  \
            const __half* xp_ = xg + (size_t)(kb) * KB;                         \
            const __half* wp_ = wg_p + (size_t)(kb) * 4 * HH * KB;              \
            cp16(XS_ADDR(s_, l_row, l_colh), xp_);                              \
            cp16(XS_ADDR(s_, l_row, l_colh + 8), xp_ + 8);                      \
            cp16(WS_ADDR(s_, l_row, l_colh), wp_);                              \
            cp16(WS_ADDR(s_, l_row, l_colh + 8), wp_ + 8);                      \
            asm volatile("cp.async.commit_group;" ::: "memory");                \
        }

        float acc[4][2][2][4];
#pragma unroll
        for (int g = 0; g < 4; g++)
#pragma unroll
            for (int mt = 0; mt < 2; mt++)
#pragma unroll
                for (int dt = 0; dt < 2; dt++)
#pragma unroll
                    for (int j = 0; j < 4; j++) acc[g][mt][dt][j] = 0.f;

        LOAD_STAGE(0);
        LOAD_STAGE(1);
        LOAD_STAGE(2);

#pragma unroll
        for (int kb = 0; kb < NKB; kb++) {
            int s = kb & 3;
            if (kb < NKB - 3) {
                WAITG(2);
            } else if (kb == NKB - 3) {
                WAITG(2);
            } else if (kb == NKB - 2) {
                WAITG(1);
            } else {
                WAITG(0);
            }
            __syncthreads();
            if (kb + 3 < NKB) LOAD_STAGE(kb + 3);

#pragma unroll
            for (int ks = 0; ks < 2; ks++) {
                int colh = ks * 16 + fcolh;
                uint32_t a[2][4];
                ldm_x4(a[0], XS_ADDR(s, m0 + 0 + frow, colh));
                ldm_x4(a[1], XS_ADDR(s, m0 + 16 + frow, colh));
                uint32_t b[4][4];
#pragma unroll
                for (int g = 0; g < 4; g++)
                    ldm_x4(b[g], WS_ADDR(s, g * 32 + d0 + frow, colh));
#pragma unroll
                for (int g = 0; g < 4; g++)
#pragma unroll
                    for (int mt = 0; mt < 2; mt++)
#pragma unroll
                        for (int dt = 0; dt < 2; dt++)
                            mma_f16(acc[g][mt][dt], a[mt], b[g][dt], b[g][dt + 2]);
            }
        }

        // ---- fused LSTM epilogue (gate order: i, o, f, cell) ----------------
#pragma unroll
        for (int dt = 0; dt < 2; dt++) {
            int d = d_base + d0 + dt * 8 + tig * 2;
            float2 bi = *(const float2*)&bias[0 * HH + d];
            float2 bo = *(const float2*)&bias[1 * HH + d];
            float2 bf = *(const float2*)&bias[2 * HH + d];
            float2 bg = *(const float2*)&bias[3 * HH + d];
#pragma unroll
            for (int mt = 0; mt < 2; mt++) {
#pragma unroll
                for (int rr = 0; rr < 2; rr++) {
                    int m = m_base + m0 + mt * 16 + gid + rr * 8;
                    size_t off = (size_t)m * HH + d;
                    float2 cv = *(const float2*)&c_src[off];

                    float i0 = sigf(acc[0][mt][dt][rr * 2 + 0] + bi.x);
                    float i1 = sigf(acc[0][mt][dt][rr * 2 + 1] + bi.y);
                    float o0 = sigf(acc[1][mt][dt][rr * 2 + 0] + bo.x);
                    float o1 = sigf(acc[1][mt][dt][rr * 2 + 1] + bo.y);
                    float f0 = sigf(acc[2][mt][dt][rr * 2 + 0] + bf.x);
                    float f1 = sigf(acc[2][mt][dt][rr * 2 + 1] + bf.y);
                    float g0 = tanhf(acc[3][mt][dt][rr * 2 + 0] + bg.x);
                    float g1 = tanhf(acc[3][mt][dt][rr * 2 + 1] + bg.y);

                    float cn0 = f0 * cv.x + i0 * g0;
                    float cn1 = f1 * cv.y + i1 * g1;
                    *(float2*)&c_dst[off] = make_float2(cn0, cn1);
                    *(float2*)&h_dst[off] = make_float2(o0 * tanhf(cn0), o1 * tanhf(cn1));
                }
            }
        }
        __syncthreads();
#undef LOAD_STAGE
    }
#undef XS_ADDR
#undef WS_ADDR
}

// ---------------------------------------------------------------------------
extern "C" void kernel_launch(void* const* d_in, const int* in_sizes, int n_in,
                              void* d_out, int out_size) {
    const float* node_hidden = (const float*)d_in[0];
    const float* cell        = (const float*)d_in[1];
    const float* w_in        = (const float*)d_in[2];
    const float* w_out       = (const float*)d_in[3];
    const float* u_in        = (const float*)d_in[4];
    const float* u_out       = (const float*)d_in[5];
    const float* b           = (const float*)d_in[6];
    const float* in_msk      = (const float*)d_in[7];
    const float* out_msk     = (const float*)d_in[8];
    const int*   in_idx      = (const int*)d_in[9];
    const int*   out_idx     = (const int*)d_in[10];
    float* out = (float*)d_out;

    cudaFuncSetAttribute(gemm_lstm_mma,
                         cudaFuncAttributeMaxDynamicSharedMemorySize, SMEM_GEMM);

    prep_kernel<<<(NKB * 4 * HH * KB) / 256, 256>>>(w_in, w_out, u_in, u_out);

    // Layer 1
    agg_kernel<<<MM / 4, 256>>>(node_hidden, 1, in_idx, in_msk, out_idx, out_msk);
    gemm_lstm_mma<<<GRID_G, 256, SMEM_GEMM>>>(b, cell, out, 0);

    // Layer 2
    agg_kernel<<<MM / 4, 256>>>(nullptr, 0, in_idx, in_msk, out_idx, out_msk);
    gemm_lstm_mma<<<GRID_G, 256, SMEM_GEMM>>>(b, nullptr, out, 1);
}

// round 12
// speedup vs baseline: 1.2753x; 1.0489x over previous
#include <cuda_runtime.h>
#include <cuda_fp16.h>
#include <math.h>
#include <stdint.h>

// Problem constants (fixed by setup_inputs)
#define BB 8
#define NN 2000
#define HH 128
#define KK 32
#define MM (BB * NN)        // 16000 rows
#define KDIM 384            // concat [in_agg | out_agg | h]
#define KB 32               // k per pipeline stage (halfs)
#define NKB (KDIM / KB)     // 12 stages
#define ROWB 80             // padded smem row bytes (64 data + 16 pad)
#define STAGE_B (128 * ROWB)         // 10240 bytes per operand stage
#define SMEM_GEMM (4 * 2 * STAGE_B)  // 81920 bytes

#define NTILE 125           // 16000 / 128 exact
#define NTASK (NTILE * 4)   // 500 (tile x dblock) per layer
#define GRID_G 296          // 2 CTAs/SM x 148 SMs

// ---- scratch (device globals; no allocation allowed) ----------------------
__device__ __half g_Xh[MM * KDIM];             // X rows fp16, [m][k]
__device__ __half g_Wh[NKB * 4 * HH * KB];     // [kb][g][d][k] fp16
__device__ float  g_h[MM * HH];                // h after layer 1 (fp32)
__device__ float  g_c[MM * HH];                // cell scratch (fp32)
__device__ int    g_task[2];                   // work-steal counters per layer

// ---- helpers ---------------------------------------------------------------
__device__ __forceinline__ uint32_t smem_u32(const void* p) {
    uint32_t a;
    asm("{ .reg .u64 t; cvta.to.shared.u64 t, %1; cvt.u32.u64 %0, t; }" : "=r"(a) : "l"(p));
    return a;
}

__device__ __forceinline__ void cp16(uint32_t s, const void* g) {
    asm volatile("cp.async.cg.shared.global [%0], [%1], 16;" :: "r"(s), "l"(g));
}

__device__ __forceinline__ void ldm_x4(uint32_t* r, uint32_t addr) {
    asm volatile("ldmatrix.sync.aligned.m8n8.x4.shared.b16 {%0,%1,%2,%3}, [%4];"
                 : "=r"(r[0]), "=r"(r[1]), "=r"(r[2]), "=r"(r[3]) : "r"(addr));
}

__device__ __forceinline__ void mma_f16(float* c, const uint32_t* a,
                                        uint32_t b0, uint32_t b1) {
    asm volatile(
        "mma.sync.aligned.m16n8k16.row.col.f32.f16.f16.f32 "
        "{%0,%1,%2,%3}, {%4,%5,%6,%7}, {%8,%9}, {%0,%1,%2,%3};"
        : "+f"(c[0]), "+f"(c[1]), "+f"(c[2]), "+f"(c[3])
        : "r"(a[0]), "r"(a[1]), "r"(a[2]), "r"(a[3]), "r"(b0), "r"(b1));
}

__device__ __forceinline__ float sigf(float x) { return 1.0f / (1.0f + expf(-x)); }

#define WAITG(n) asm volatile("cp.async.wait_group %0;" :: "n"(n) : "memory")

// ---------------------------------------------------------------------------
// prep: g_Wh[kb][g][d][k] = half( A_g[d][kb*32+k] ); block 0 resets counters.
// ---------------------------------------------------------------------------
__global__ void prep_kernel(const float* __restrict__ w_in,
                            const float* __restrict__ w_out,
                            const float* __restrict__ u_in,
                            const float* __restrict__ u_out) {
    int idx = blockIdx.x * blockDim.x + threadIdx.x;   // 196608 exact
    if (blockIdx.x == 0 && threadIdx.x < 2) g_task[threadIdx.x] = 0;
    int k = idx & 31;
    int d = (idx >> 5) & 127;
    int g = (idx >> 12) & 3;
    int kb = idx >> 14;
    int kg = kb * KB + k;
    float v;
    if (kg < 128) {
        v = w_in[(g * 128 + kg) * 128 + d];
    } else if (kg < 256) {
        v = w_out[(g * 128 + (kg - 128)) * 128 + d];
    } else {
        int kk = kg - 256;
        v = u_in[(g * 128 + kk) * 128 + d] + u_out[(g * 128 + kk) * 128 + d];
    }
    g_Wh[idx] = __float2half_rn(v);
}

// ---------------------------------------------------------------------------
// Aggregation: TWO warps per node (one per edge set). 256 threads = 8 warps
// = 4 nodes. 8-deep explicit load batching for MLP (8 LDG.128 in flight).
// ---------------------------------------------------------------------------
__global__ void __launch_bounds__(256, 4)
agg_kernel(const float* __restrict__ h_ext, int use_ext,
           const int*   __restrict__ in_idx,
           const float* __restrict__ in_msk,
           const int*   __restrict__ out_idx,
           const float* __restrict__ out_msk) {
    const float* h_src = use_ext ? h_ext : g_h;
    __shared__ int   s_idx[8][KK];
    __shared__ float s_msk[8][KK];

    int tid = threadIdx.x;
    int wid = tid >> 5;
    int lane = tid & 31;
    int es = wid & 1;                 // 0 = in, 1 = out
    int bn = blockIdx.x * 4 + (wid >> 1);

    {
        const int*   ip = es ? out_idx : in_idx;
        const float* mp = es ? out_msk : in_msk;
        s_idx[wid][lane] = ip[bn * KK + lane];
        s_msk[wid][lane] = mp[bn * KK + lane];
    }
    __syncwarp();

    int base_b = (bn / NN) * NN;
    const float4* h4 = (const float4*)h_src;

    float4 a = make_float4(0.f, 0.f, 0.f, 0.f);

#pragma unroll
    for (int kc = 0; kc < KK; kc += 8) {
        float4 v[8];
        float  m[8];
#pragma unroll
        for (int u = 0; u < 8; u++) {
            int j = s_idx[wid][kc + u];
            m[u] = s_msk[wid][kc + u];
            v[u] = h4[(size_t)(base_b + j) * 32 + lane];
        }
#pragma unroll
        for (int u = 0; u < 8; u++) {
            a.x += m[u] * v[u].x;
            a.y += m[u] * v[u].y;
            a.z += m[u] * v[u].z;
            a.w += m[u] * v[u].w;
        }
    }

    __half2* X2 = (__half2*)(g_Xh + (size_t)bn * KDIM);
    X2[es * 64 + lane * 2 + 0] = __floats2half2_rn(a.x, a.y);
    X2[es * 64 + lane * 2 + 1] = __floats2half2_rn(a.z, a.w);
    if (es == 0) {
        float4 hv = h4[(size_t)bn * 32 + lane];
        X2[2 * 64 + lane * 2 + 0] = __floats2half2_rn(hv.x, hv.y);
        X2[2 * 64 + lane * 2 + 1] = __floats2half2_rn(hv.z, hv.w);
    }
}

// ---------------------------------------------------------------------------
// fp16 mma.sync GEMM + fused LSTM. Persistent 296-CTA kernel, work-stealing
// (tile, dblock) tasks. Next task's first 3 pipeline stages are issued BEFORE
// the current epilogue, so the epilogue overlaps the next task's loads.
// ---------------------------------------------------------------------------
__global__ void __launch_bounds__(256, 2)
gemm_lstm_mma(const float* __restrict__ bias,
              const float* __restrict__ c_ext,
              float* __restrict__ h_final,
              int layer) {
    const float* c_src = layer ? g_c : c_ext;
    float* c_dst = g_c;
    float* h_dst = layer ? h_final : g_h;

    extern __shared__ char smem[];
    uint32_t xs_u = smem_u32(smem);
    uint32_t ws_u = xs_u + 4 * STAGE_B;
    __shared__ int s_next;

    int tid = threadIdx.x;
    int wid = tid >> 5;
    int lane = tid & 31;
    int m0 = (wid & 3) * 32;
    int d0 = (wid >> 2) * 16;

#define XS_ADDR(s, row, colh) (xs_u + (uint32_t)((s) * STAGE_B + (row) * ROWB + (colh) * 2))
#define WS_ADDR(s, row, colh) (ws_u + (uint32_t)((s) * STAGE_B + (row) * ROWB + (colh) * 2))

    // loader lanes: row = tid>>1, base col = (tid&1)*16 halfs; 32B per operand
    int l_row = tid >> 1;
    int l_colh = (tid & 1) * 16;
    int wg = l_row >> 5;
    int wdl = l_row & 31;

    int frow = (lane & 7) + ((lane >> 3) & 1) * 8;
    int fcolh = (lane >> 4) * 8;
    int gid = lane >> 2;
    int tig = lane & 3;

#define TASK_PTRS(task, xg, wp)                                                 \
    const __half* xg = g_Xh + (size_t)(((task) >> 2) * 128 + l_row) * KDIM + l_colh; \
    const __half* wp = g_Wh + ((size_t)(wg * HH) + ((task) & 3) * 32 + wdl) * KB + l_colh;

#define LOAD_STAGE(xg, wp, kb)                                                  \
    {                                                                           \
        int s_ = (kb) & 3;                                                      \
        const __half* xp_ = (xg) + (size_t)(kb) * KB;                           \
        const __half* wp_ = (wp) + (size_t)(kb) * 4 * HH * KB;                  \
        cp16(XS_ADDR(s_, l_row, l_colh), xp_);                                  \
        cp16(XS_ADDR(s_, l_row, l_colh + 8), xp_ + 8);                          \
        cp16(WS_ADDR(s_, l_row, l_colh), wp_);                                  \
        cp16(WS_ADDR(s_, l_row, l_colh + 8), wp_ + 8);                          \
        asm volatile("cp.async.commit_group;" ::: "memory");                    \
    }

    // fetch first task; prime pipeline
    if (tid == 0) s_next = atomicAdd(&g_task[layer], 1);
    __syncthreads();
    int task = s_next;
    if (task >= NTASK) return;
    const __half* cur_x;
    const __half* cur_w;
    {
        TASK_PTRS(task, xg0, wp0);
        cur_x = xg0; cur_w = wp0;
        LOAD_STAGE(cur_x, cur_w, 0);
        LOAD_STAGE(cur_x, cur_w, 1);
        LOAD_STAGE(cur_x, cur_w, 2);
    }

    for (;;) {
        // claim next task (sync first: everyone has read s_next already)
        __syncthreads();
        if (tid == 0) s_next = atomicAdd(&g_task[layer], 1);

        float acc[4][2][2][4];
#pragma unroll
        for (int g = 0; g < 4; g++)
#pragma unroll
            for (int mt = 0; mt < 2; mt++)
#pragma unroll
                for (int dt = 0; dt < 2; dt++)
#pragma unroll
                    for (int j = 0; j < 4; j++) acc[g][mt][dt][j] = 0.f;

#pragma unroll
        for (int kb = 0; kb < NKB; kb++) {
            int s = kb & 3;
            if (kb < NKB - 2) {
                WAITG(2);
            } else if (kb == NKB - 2) {
                WAITG(1);
            } else {
                WAITG(0);
            }
            __syncthreads();
            if (kb + 3 < NKB) LOAD_STAGE(cur_x, cur_w, kb + 3);

#pragma unroll
            for (int ks = 0; ks < 2; ks++) {
                int colh = ks * 16 + fcolh;
                uint32_t a[2][4];
                ldm_x4(a[0], XS_ADDR(s, m0 + 0 + frow, colh));
                ldm_x4(a[1], XS_ADDR(s, m0 + 16 + frow, colh));
                uint32_t b[4][4];
#pragma unroll
                for (int g = 0; g < 4; g++)
                    ldm_x4(b[g], WS_ADDR(s, g * 32 + d0 + frow, colh));
#pragma unroll
                for (int g = 0; g < 4; g++)
#pragma unroll
                    for (int mt = 0; mt < 2; mt++)
#pragma unroll
                        for (int dt = 0; dt < 2; dt++)
                            mma_f16(acc[g][mt][dt], a[mt], b[g][dt], b[g][dt + 2]);
            }
        }

        // all warps done reading stages 0..2 of this task
        __syncthreads();
        int next = s_next;
        if (next < NTASK) {
            TASK_PTRS(next, xgn, wpn);
            cur_x = xgn; cur_w = wpn;
            LOAD_STAGE(cur_x, cur_w, 0);
            LOAD_STAGE(cur_x, cur_w, 1);
            LOAD_STAGE(cur_x, cur_w, 2);
        }

        // ---- fused LSTM epilogue (gate order: i, o, f, cell) ----------------
        int m_base = (task >> 2) * 128;
        int d_base = (task & 3) * 32;
#pragma unroll
        for (int dt = 0; dt < 2; dt++) {
            int d = d_base + d0 + dt * 8 + tig * 2;
            float2 bi = *(const float2*)&bias[0 * HH + d];
            float2 bo = *(const float2*)&bias[1 * HH + d];
            float2 bf = *(const float2*)&bias[2 * HH + d];
            float2 bg = *(const float2*)&bias[3 * HH + d];
#pragma unroll
            for (int mt = 0; mt < 2; mt++) {
#pragma unroll
                for (int rr = 0; rr < 2; rr++) {
                    int m = m_base + m0 + mt * 16 + gid + rr * 8;
                    size_t off = (size_t)m * HH + d;
                    float2 cv = *(const float2*)&c_src[off];

                    float i0 = sigf(acc[0][mt][dt][rr * 2 + 0] + bi.x);
                    float i1 = sigf(acc[0][mt][dt][rr * 2 + 1] + bi.y);
                    float o0 = sigf(acc[1][mt][dt][rr * 2 + 0] + bo.x);
                    float o1 = sigf(acc[1][mt][dt][rr * 2 + 1] + bo.y);
                    float f0 = sigf(acc[2][mt][dt][rr * 2 + 0] + bf.x);
                    float f1 = sigf(acc[2][mt][dt][rr * 2 + 1] + bf.y);
                    float g0 = tanhf(acc[3][mt][dt][rr * 2 + 0] + bg.x);
                    float g1 = tanhf(acc[3][mt][dt][rr * 2 + 1] + bg.y);

                    float cn0 = f0 * cv.x + i0 * g0;
                    float cn1 = f1 * cv.y + i1 * g1;
                    *(float2*)&c_dst[off] = make_float2(cn0, cn1);
                    *(float2*)&h_dst[off] = make_float2(o0 * tanhf(cn0), o1 * tanhf(cn1));
                }
            }
        }

        if (next >= NTASK) return;
        task = next;
    }
#undef XS_ADDR
#undef WS_ADDR
#undef LOAD_STAGE
#undef TASK_PTRS
}

// ---------------------------------------------------------------------------
extern "C" void kernel_launch(void* const* d_in, const int* in_sizes, int n_in,
                              void* d_out, int out_size) {
    const float* node_hidden = (const float*)d_in[0];
    const float* cell        = (const float*)d_in[1];
    const float* w_in        = (const float*)d_in[2];
    const float* w_out       = (const float*)d_in[3];
    const float* u_in        = (const float*)d_in[4];
    const float* u_out       = (const float*)d_in[5];
    const float* b           = (const float*)d_in[6];
    const float* in_msk      = (const float*)d_in[7];
    const float* out_msk     = (const float*)d_in[8];
    const int*   in_idx      = (const int*)d_in[9];
    const int*   out_idx     = (const int*)d_in[10];
    float* out = (float*)d_out;

    cudaFuncSetAttribute(gemm_lstm_mma,
                         cudaFuncAttributeMaxDynamicSharedMemorySize, SMEM_GEMM);

    prep_kernel<<<(NKB * 4 * HH * KB) / 256, 256>>>(w_in, w_out, u_in, u_out);

    // Layer 1
    agg_kernel<<<MM / 4, 256>>>(node_hidden, 1, in_idx, in_msk, out_idx, out_msk);
    gemm_lstm_mma<<<GRID_G, 256, SMEM_GEMM>>>(b, cell, out, 0);

    // Layer 2
    agg_kernel<<<MM / 4, 256>>>(nullptr, 0, in_idx, in_msk, out_idx, out_msk);
    gemm_lstm_mma<<<GRID_G, 256, SMEM_GEMM>>>(b, nullptr, out, 1);
}

// round 13
// speedup vs baseline: 1.2779x; 1.0020x over previous
#include <cuda_runtime.h>
#include <cuda_fp16.h>
#include <math.h>
#include <stdint.h>

// Problem constants (fixed by setup_inputs)
#define BB 8
#define NN 2000
#define HH 128
#define KK 32
#define MM (BB * NN)        // 16000 rows
#define KDIM 384            // concat [in_agg | out_agg | h]
#define KB 32               // k per pipeline stage (halfs)
#define NKB (KDIM / KB)     // 12 stages
#define ROWB 80             // padded smem row bytes (64 data + 16 pad)
#define XSTAGE_B (64 * ROWB)          // 5120 B per X stage (64 m-rows)
#define WSTAGE_B (128 * ROWB)         // 10240 B per W stage (4g x 32d rows)
#define SMEM_GEMM (4 * (XSTAGE_B + WSTAGE_B))   // 61440 B

#define NTILE 250           // 16000 / 64 exact
#define NTASK (NTILE * 4)   // 1000 (tile x dblock) per layer
#define GRID_G 296          // 2 CTAs/SM x 148 SMs

// ---- scratch (device globals; no allocation allowed) ----------------------
__device__ __half g_Xh[MM * KDIM];             // X rows fp16, [m][k]
__device__ __half g_Wh[NKB * 4 * HH * KB];     // [kb][g][d][k] fp16
__device__ float  g_h[MM * HH];                // h after layer 1 (fp32)
__device__ float  g_c[MM * HH];                // cell scratch (fp32)
__device__ int    g_task[2];                   // work-steal counters per layer

// ---- helpers ---------------------------------------------------------------
__device__ __forceinline__ uint32_t smem_u32(const void* p) {
    uint32_t a;
    asm("{ .reg .u64 t; cvta.to.shared.u64 t, %1; cvt.u32.u64 %0, t; }" : "=r"(a) : "l"(p));
    return a;
}

__device__ __forceinline__ void cp16(uint32_t s, const void* g) {
    asm volatile("cp.async.cg.shared.global [%0], [%1], 16;" :: "r"(s), "l"(g));
}

__device__ __forceinline__ void ldm_x4(uint32_t* r, uint32_t addr) {
    asm volatile("ldmatrix.sync.aligned.m8n8.x4.shared.b16 {%0,%1,%2,%3}, [%4];"
                 : "=r"(r[0]), "=r"(r[1]), "=r"(r[2]), "=r"(r[3]) : "r"(addr));
}

__device__ __forceinline__ void mma_f16(float* c, const uint32_t* a,
                                        uint32_t b0, uint32_t b1) {
    asm volatile(
        "mma.sync.aligned.m16n8k16.row.col.f32.f16.f16.f32 "
        "{%0,%1,%2,%3}, {%4,%5,%6,%7}, {%8,%9}, {%0,%1,%2,%3};"
        : "+f"(c[0]), "+f"(c[1]), "+f"(c[2]), "+f"(c[3])
        : "r"(a[0]), "r"(a[1]), "r"(a[2]), "r"(a[3]), "r"(b0), "r"(b1));
}

__device__ __forceinline__ float sigf(float x) { return 1.0f / (1.0f + expf(-x)); }

#define WAITG(n) asm volatile("cp.async.wait_group %0;" :: "n"(n) : "memory")

// ---------------------------------------------------------------------------
// prep: g_Wh[kb][g][d][k] = half( A_g[d][kb*32+k] ); block 0 resets counters.
// ---------------------------------------------------------------------------
__global__ void prep_kernel(const float* __restrict__ w_in,
                            const float* __restrict__ w_out,
                            const float* __restrict__ u_in,
                            const float* __restrict__ u_out) {
    int idx = blockIdx.x * blockDim.x + threadIdx.x;   // 196608 exact
    if (blockIdx.x == 0 && threadIdx.x < 2) g_task[threadIdx.x] = 0;
    int k = idx & 31;
    int d = (idx >> 5) & 127;
    int g = (idx >> 12) & 3;
    int kb = idx >> 14;
    int kg = kb * KB + k;
    float v;
    if (kg < 128) {
        v = w_in[(g * 128 + kg) * 128 + d];
    } else if (kg < 256) {
        v = w_out[(g * 128 + (kg - 128)) * 128 + d];
    } else {
        int kk = kg - 256;
        v = u_in[(g * 128 + kk) * 128 + d] + u_out[(g * 128 + kk) * 128 + d];
    }
    g_Wh[idx] = __float2half_rn(v);
}

// ---------------------------------------------------------------------------
// Aggregation: TWO warps per node (one per edge set). 256 threads = 8 warps
// = 4 nodes. 8-deep explicit load batching for MLP (8 LDG.128 in flight).
// ---------------------------------------------------------------------------
__global__ void __launch_bounds__(256, 4)
agg_kernel(const float* __restrict__ h_ext, int use_ext,
           const int*   __restrict__ in_idx,
           const float* __restrict__ in_msk,
           const int*   __restrict__ out_idx,
           const float* __restrict__ out_msk) {
    const float* h_src = use_ext ? h_ext : g_h;
    __shared__ int   s_idx[8][KK];
    __shared__ float s_msk[8][KK];

    int tid = threadIdx.x;
    int wid = tid >> 5;
    int lane = tid & 31;
    int es = wid & 1;                 // 0 = in, 1 = out
    int bn = blockIdx.x * 4 + (wid >> 1);

    {
        const int*   ip = es ? out_idx : in_idx;
        const float* mp = es ? out_msk : in_msk;
        s_idx[wid][lane] = ip[bn * KK + lane];
        s_msk[wid][lane] = mp[bn * KK + lane];
    }
    __syncwarp();

    int base_b = (bn / NN) * NN;
    const float4* h4 = (const float4*)h_src;

    float4 a = make_float4(0.f, 0.f, 0.f, 0.f);

#pragma unroll
    for (int kc = 0; kc < KK; kc += 8) {
        float4 v[8];
        float  m[8];
#pragma unroll
        for (int u = 0; u < 8; u++) {
            int j = s_idx[wid][kc + u];
            m[u] = s_msk[wid][kc + u];
            v[u] = h4[(size_t)(base_b + j) * 32 + lane];
        }
#pragma unroll
        for (int u = 0; u < 8; u++) {
            a.x += m[u] * v[u].x;
            a.y += m[u] * v[u].y;
            a.z += m[u] * v[u].z;
            a.w += m[u] * v[u].w;
        }
    }

    __half2* X2 = (__half2*)(g_Xh + (size_t)bn * KDIM);
    X2[es * 64 + lane * 2 + 0] = __floats2half2_rn(a.x, a.y);
    X2[es * 64 + lane * 2 + 1] = __floats2half2_rn(a.z, a.w);
    if (es == 0) {
        float4 hv = h4[(size_t)bn * 32 + lane];
        X2[2 * 64 + lane * 2 + 0] = __floats2half2_rn(hv.x, hv.y);
        X2[2 * 64 + lane * 2 + 1] = __floats2half2_rn(hv.z, hv.w);
    }
}

// ---------------------------------------------------------------------------
// fp16 mma.sync GEMM + fused LSTM. Persistent 296-CTA work-stealing kernel.
// Task = 64m x 32d x 4 gates (1000 tasks/layer for fine-grained balance).
// 8 warps: warp = 16m x 16d x 4g. 4-deep cp.async pipeline; next task's first
// stages issued before the current epilogue (epilogue overlaps loads).
// ---------------------------------------------------------------------------
__global__ void __launch_bounds__(256, 2)
gemm_lstm_mma(const float* __restrict__ bias,
              const float* __restrict__ c_ext,
              float* __restrict__ h_final,
              int layer) {
    const float* c_src = layer ? g_c : c_ext;
    float* c_dst = g_c;
    float* h_dst = layer ? h_final : g_h;

    extern __shared__ char smem[];
    uint32_t xs_u = smem_u32(smem);
    uint32_t ws_u = xs_u + 4 * XSTAGE_B;
    __shared__ int s_next;

    int tid = threadIdx.x;
    int wid = tid >> 5;
    int lane = tid & 31;
    int m0 = (wid & 3) * 16;          // warp m-group (4 x 16 rows)
    int d0 = (wid >> 2) * 16;         // warp d-group (2 x 16 cols)

#define XS_ADDR(s, row, colh) (xs_u + (uint32_t)((s) * XSTAGE_B + (row) * ROWB + (colh) * 2))
#define WS_ADDR(s, row, colh) (ws_u + (uint32_t)((s) * WSTAGE_B + (row) * ROWB + (colh) * 2))

    // X loader: 64 rows x 64B; 4 threads/row x 16B
    int lx_row = tid >> 2;
    int lx_colh = (tid & 3) * 8;
    // W loader: 128 rows x 64B; 2 threads/row x 32B
    int lw_row = tid >> 1;
    int lw_colh = (tid & 1) * 16;
    int wg = lw_row >> 5;
    int wdl = lw_row & 31;

    int frow = (lane & 7) + ((lane >> 3) & 1) * 8;
    int fcolh = (lane >> 4) * 8;
    int gid = lane >> 2;
    int tig = lane & 3;

#define TASK_PTRS(task, xg, wp)                                                 \
    const __half* xg = g_Xh + (size_t)(((task) >> 2) * 64 + lx_row) * KDIM + lx_colh; \
    const __half* wp = g_Wh + ((size_t)(wg * HH) + ((task) & 3) * 32 + wdl) * KB + lw_colh;

#define LOAD_STAGE(xg, wp, kb)                                                  \
    {                                                                           \
        int s_ = (kb) & 3;                                                      \
        const __half* xp_ = (xg) + (size_t)(kb) * KB;                           \
        const __half* wp_ = (wp) + (size_t)(kb) * 4 * HH * KB;                  \
        cp16(XS_ADDR(s_, lx_row, lx_colh), xp_);                                \
        cp16(WS_ADDR(s_, lw_row, lw_colh), wp_);                                \
        cp16(WS_ADDR(s_, lw_row, lw_colh + 8), wp_ + 8);                        \
        asm volatile("cp.async.commit_group;" ::: "memory");                    \
    }

    // fetch first task; prime pipeline
    if (tid == 0) s_next = atomicAdd(&g_task[layer], 1);
    __syncthreads();
    int task = s_next;
    if (task >= NTASK) return;
    const __half* cur_x;
    const __half* cur_w;
    {
        TASK_PTRS(task, xg0, wp0);
        cur_x = xg0; cur_w = wp0;
        LOAD_STAGE(cur_x, cur_w, 0);
        LOAD_STAGE(cur_x, cur_w, 1);
        LOAD_STAGE(cur_x, cur_w, 2);
    }

    for (;;) {
        // claim next task (sync first: everyone has consumed s_next)
        __syncthreads();
        if (tid == 0) s_next = atomicAdd(&g_task[layer], 1);

        float acc[4][2][4];    // [gate][dt][c0..c3]
#pragma unroll
        for (int g = 0; g < 4; g++)
#pragma unroll
            for (int dt = 0; dt < 2; dt++)
#pragma unroll
                for (int j = 0; j < 4; j++) acc[g][dt][j] = 0.f;

#pragma unroll
        for (int kb = 0; kb < NKB; kb++) {
            int s = kb & 3;
            if (kb < NKB - 2) {
                WAITG(2);
            } else if (kb == NKB - 2) {
                WAITG(1);
            } else {
                WAITG(0);
            }
            __syncthreads();
            if (kb + 3 < NKB) LOAD_STAGE(cur_x, cur_w, kb + 3);

#pragma unroll
            for (int ks = 0; ks < 2; ks++) {
                int colh = ks * 16 + fcolh;
                uint32_t a[4];
                ldm_x4(a, XS_ADDR(s, m0 + frow, colh));
                uint32_t b[4][4];
#pragma unroll
                for (int g = 0; g < 4; g++)
                    ldm_x4(b[g], WS_ADDR(s, g * 32 + d0 + frow, colh));
#pragma unroll
                for (int g = 0; g < 4; g++)
#pragma unroll
                    for (int dt = 0; dt < 2; dt++)
                        mma_f16(acc[g][dt], a, b[g][dt], b[g][dt + 2]);
            }
        }

        // all warps done reading this task's stages
        __syncthreads();
        int next = s_next;
        if (next < NTASK) {
            TASK_PTRS(next, xgn, wpn);
            cur_x = xgn; cur_w = wpn;
            LOAD_STAGE(cur_x, cur_w, 0);
            LOAD_STAGE(cur_x, cur_w, 1);
            LOAD_STAGE(cur_x, cur_w, 2);
        }

        // ---- fused LSTM epilogue (gate order: i, o, f, cell) ----------------
        int m_base = (task >> 2) * 64;
        int d_base = (task & 3) * 32;
#pragma unroll
        for (int dt = 0; dt < 2; dt++) {
            int d = d_base + d0 + dt * 8 + tig * 2;
            float2 bi = *(const float2*)&bias[0 * HH + d];
            float2 bo = *(const float2*)&bias[1 * HH + d];
            float2 bf = *(const float2*)&bias[2 * HH + d];
            float2 bg = *(const float2*)&bias[3 * HH + d];
#pragma unroll
            for (int rr = 0; rr < 2; rr++) {
                int m = m_base + m0 + gid + rr * 8;
                size_t off = (size_t)m * HH + d;
                float2 cv = *(const float2*)&c_src[off];

                float i0 = sigf(acc[0][dt][rr * 2 + 0] + bi.x);
                float i1 = sigf(acc[0][dt][rr * 2 + 1] + bi.y);
                float o0 = sigf(acc[1][dt][rr * 2 + 0] + bo.x);
                float o1 = sigf(acc[1][dt][rr * 2 + 1] + bo.y);
                float f0 = sigf(acc[2][dt][rr * 2 + 0] + bf.x);
                float f1 = sigf(acc[2][dt][rr * 2 + 1] + bf.y);
                float g0 = tanhf(acc[3][dt][rr * 2 + 0] + bg.x);
                float g1 = tanhf(acc[3][dt][rr * 2 + 1] + bg.y);

                float cn0 = f0 * cv.x + i0 * g0;
                float cn1 = f1 * cv.y + i1 * g1;
                *(float2*)&c_dst[off] = make_float2(cn0, cn1);
                *(float2*)&h_dst[off] = make_float2(o0 * tanhf(cn0), o1 * tanhf(cn1));
            }
        }

        if (next >= NTASK) return;
        task = next;
    }
#undef XS_ADDR
#undef WS_ADDR
#undef LOAD_STAGE
#undef TASK_PTRS
}

// ---------------------------------------------------------------------------
extern "C" void kernel_launch(void* const* d_in, const int* in_sizes, int n_in,
                              void* d_out, int out_size) {
    const float* node_hidden = (const float*)d_in[0];
    const float* cell        = (const float*)d_in[1];
    const float* w_in        = (const float*)d_in[2];
    const float* w_out       = (const float*)d_in[3];
    const float* u_in        = (const float*)d_in[4];
    const float* u_out       = (const float*)d_in[5];
    const float* b           = (const float*)d_in[6];
    const float* in_msk      = (const float*)d_in[7];
    const float* out_msk     = (const float*)d_in[8];
    const int*   in_idx      = (const int*)d_in[9];
    const int*   out_idx     = (const int*)d_in[10];
    float* out = (float*)d_out;

    cudaFuncSetAttribute(gemm_lstm_mma,
                         cudaFuncAttributeMaxDynamicSharedMemorySize, SMEM_GEMM);

    prep_kernel<<<(NKB * 4 * HH * KB) / 256, 256>>>(w_in, w_out, u_in, u_out);

    // Layer 1
    agg_kernel<<<MM / 4, 256>>>(node_hidden, 1, in_idx, in_msk, out_idx, out_msk);
    gemm_lstm_mma<<<GRID_G, 256, SMEM_GEMM>>>(b, cell, out, 0);

    // Layer 2
    agg_kernel<<<MM / 4, 256>>>(nullptr, 0, in_idx, in_msk, out_idx, out_msk);
    gemm_lstm_mma<<<GRID_G, 256, SMEM_GEMM>>>(b, nullptr, out, 1);
}

// round 14
// speedup vs baseline: 1.3035x; 1.0200x over previous
#include <cuda_runtime.h>
#include <cuda_fp16.h>
#include <math.h>
#include <stdint.h>

// Problem constants (fixed by setup_inputs)
#define BB 8
#define NN 2000
#define HH 128
#define KK 32
#define MM (BB * NN)        // 16000 rows
#define KDIM 384            // concat [in_agg | out_agg | h]
#define KB 32               // k per pipeline stage (halfs)
#define NKB (KDIM / KB)     // 12 stages
#define ROWB 80             // padded smem row bytes (64 data + 16 pad)
#define XSTAGE_B (64 * ROWB)          // 5120 B per X stage (64 m-rows)
#define WSTAGE_B (128 * ROWB)         // 10240 B per W stage (4g x 32d rows)
#define SMEM_GEMM (4 * (XSTAGE_B + WSTAGE_B))   // 61440 B

#define NTILE 250           // 16000 / 64 exact
#define NTASK (NTILE * 4)   // 1000 (tile x dblock) per layer
#define GRID_G 444          // 3 CTAs/SM x 148 SMs

// ---- scratch (device globals; no allocation allowed) ----------------------
__device__ __half g_Xh[MM * KDIM];             // X rows fp16, [m][k]
__device__ __half g_Wh[NKB * 4 * HH * KB];     // [kb][g][d][k] fp16
__device__ float  g_h[MM * HH];                // h after layer 1 (fp32)
__device__ float  g_c[MM * HH];                // cell scratch (fp32)
__device__ int    g_task[2];                   // work-steal counters per layer

// ---- helpers ---------------------------------------------------------------
__device__ __forceinline__ uint32_t smem_u32(const void* p) {
    uint32_t a;
    asm("{ .reg .u64 t; cvta.to.shared.u64 t, %1; cvt.u32.u64 %0, t; }" : "=r"(a) : "l"(p));
    return a;
}

__device__ __forceinline__ void cp16(uint32_t s, const void* g) {
    asm volatile("cp.async.cg.shared.global [%0], [%1], 16;" :: "r"(s), "l"(g));
}

__device__ __forceinline__ void ldm_x4(uint32_t* r, uint32_t addr) {
    asm volatile("ldmatrix.sync.aligned.m8n8.x4.shared.b16 {%0,%1,%2,%3}, [%4];"
                 : "=r"(r[0]), "=r"(r[1]), "=r"(r[2]), "=r"(r[3]) : "r"(addr));
}

__device__ __forceinline__ void mma_f16(float* c, const uint32_t* a,
                                        uint32_t b0, uint32_t b1) {
    asm volatile(
        "mma.sync.aligned.m16n8k16.row.col.f32.f16.f16.f32 "
        "{%0,%1,%2,%3}, {%4,%5,%6,%7}, {%8,%9}, {%0,%1,%2,%3};"
        : "+f"(c[0]), "+f"(c[1]), "+f"(c[2]), "+f"(c[3])
        : "r"(a[0]), "r"(a[1]), "r"(a[2]), "r"(a[3]), "r"(b0), "r"(b1));
}

__device__ __forceinline__ float sigf(float x) { return 1.0f / (1.0f + expf(-x)); }

#define WAITG(n) asm volatile("cp.async.wait_group %0;" :: "n"(n) : "memory")

// ---------------------------------------------------------------------------
// prep: g_Wh[kb][g][d][k] = half( A_g[d][kb*32+k] ); block 0 resets counters.
// ---------------------------------------------------------------------------
__global__ void prep_kernel(const float* __restrict__ w_in,
                            const float* __restrict__ w_out,
                            const float* __restrict__ u_in,
                            const float* __restrict__ u_out) {
    int idx = blockIdx.x * blockDim.x + threadIdx.x;   // 196608 exact
    if (blockIdx.x == 0 && threadIdx.x < 2) g_task[threadIdx.x] = 0;
    int k = idx & 31;
    int d = (idx >> 5) & 127;
    int g = (idx >> 12) & 3;
    int kb = idx >> 14;
    int kg = kb * KB + k;
    float v;
    if (kg < 128) {
        v = w_in[(g * 128 + kg) * 128 + d];
    } else if (kg < 256) {
        v = w_out[(g * 128 + (kg - 128)) * 128 + d];
    } else {
        int kk = kg - 256;
        v = u_in[(g * 128 + kk) * 128 + d] + u_out[(g * 128 + kk) * 128 + d];
    }
    g_Wh[idx] = __float2half_rn(v);
}

// ---------------------------------------------------------------------------
// Aggregation: TWO warps per node (one per edge set). 256 threads = 8 warps
// = 4 nodes. 8-deep explicit load batching for MLP (8 LDG.128 in flight).
// ---------------------------------------------------------------------------
__global__ void __launch_bounds__(256, 4)
agg_kernel(const float* __restrict__ h_ext, int use_ext,
           const int*   __restrict__ in_idx,
           const float* __restrict__ in_msk,
           const int*   __restrict__ out_idx,
           const float* __restrict__ out_msk) {
    const float* h_src = use_ext ? h_ext : g_h;
    __shared__ int   s_idx[8][KK];
    __shared__ float s_msk[8][KK];

    int tid = threadIdx.x;
    int wid = tid >> 5;
    int lane = tid & 31;
    int es = wid & 1;                 // 0 = in, 1 = out
    int bn = blockIdx.x * 4 + (wid >> 1);

    {
        const int*   ip = es ? out_idx : in_idx;
        const float* mp = es ? out_msk : in_msk;
        s_idx[wid][lane] = ip[bn * KK + lane];
        s_msk[wid][lane] = mp[bn * KK + lane];
    }
    __syncwarp();

    int base_b = (bn / NN) * NN;
    const float4* h4 = (const float4*)h_src;

    float4 a = make_float4(0.f, 0.f, 0.f, 0.f);

#pragma unroll
    for (int kc = 0; kc < KK; kc += 8) {
        float4 v[8];
        float  m[8];
#pragma unroll
        for (int u = 0; u < 8; u++) {
            int j = s_idx[wid][kc + u];
            m[u] = s_msk[wid][kc + u];
            v[u] = h4[(size_t)(base_b + j) * 32 + lane];
        }
#pragma unroll
        for (int u = 0; u < 8; u++) {
            a.x += m[u] * v[u].x;
            a.y += m[u] * v[u].y;
            a.z += m[u] * v[u].z;
            a.w += m[u] * v[u].w;
        }
    }

    __half2* X2 = (__half2*)(g_Xh + (size_t)bn * KDIM);
    X2[es * 64 + lane * 2 + 0] = __floats2half2_rn(a.x, a.y);
    X2[es * 64 + lane * 2 + 1] = __floats2half2_rn(a.z, a.w);
    if (es == 0) {
        float4 hv = h4[(size_t)bn * 32 + lane];
        X2[2 * 64 + lane * 2 + 0] = __floats2half2_rn(hv.x, hv.y);
        X2[2 * 64 + lane * 2 + 1] = __floats2half2_rn(hv.z, hv.w);
    }
}

// ---------------------------------------------------------------------------
// fp16 mma.sync GEMM + fused LSTM. Persistent 444-CTA work-stealing kernel
// (3 CTAs/SM: 24 warps/SM to hide sync + LDSM bubbles).
// Task = 64m x 32d x 4 gates; warp = 16m x 16d x 4g; 4-deep cp.async pipeline;
// next task's first stages issued before the current epilogue.
// ---------------------------------------------------------------------------
__global__ void __launch_bounds__(256, 3)
gemm_lstm_mma(const float* __restrict__ bias,
              const float* __restrict__ c_ext,
              float* __restrict__ h_final,
              int layer) {
    const float* c_src = layer ? g_c : c_ext;
    float* c_dst = g_c;
    float* h_dst = layer ? h_final : g_h;

    extern __shared__ char smem[];
    uint32_t xs_u = smem_u32(smem);
    uint32_t ws_u = xs_u + 4 * XSTAGE_B;
    __shared__ int s_next;

    int tid = threadIdx.x;
    int wid = tid >> 5;
    int lane = tid & 31;
    int m0 = (wid & 3) * 16;          // warp m-group (4 x 16 rows)
    int d0 = (wid >> 2) * 16;         // warp d-group (2 x 16 cols)

#define XS_ADDR(s, row, colh) (xs_u + (uint32_t)((s) * XSTAGE_B + (row) * ROWB + (colh) * 2))
#define WS_ADDR(s, row, colh) (ws_u + (uint32_t)((s) * WSTAGE_B + (row) * ROWB + (colh) * 2))

    // X loader: 64 rows x 64B; 4 threads/row x 16B
    int lx_row = tid >> 2;
    int lx_colh = (tid & 3) * 8;
    // W loader: 128 rows x 64B; 2 threads/row x 32B
    int lw_row = tid >> 1;
    int lw_colh = (tid & 1) * 16;
    int wg = lw_row >> 5;
    int wdl = lw_row & 31;

    int frow = (lane & 7) + ((lane >> 3) & 1) * 8;
    int fcolh = (lane >> 4) * 8;
    int gid = lane >> 2;
    int tig = lane & 3;

#define TASK_PTRS(task, xg, wp)                                                 \
    const __half* xg = g_Xh + (size_t)(((task) >> 2) * 64 + lx_row) * KDIM + lx_colh; \
    const __half* wp = g_Wh + ((size_t)(wg * HH) + ((task) & 3) * 32 + wdl) * KB + lw_colh;

#define LOAD_STAGE(xg, wp, kb)                                                  \
    {                                                                           \
        int s_ = (kb) & 3;                                                      \
        const __half* xp_ = (xg) + (size_t)(kb) * KB;                           \
        const __half* wp_ = (wp) + (size_t)(kb) * 4 * HH * KB;                  \
        cp16(XS_ADDR(s_, lx_row, lx_colh), xp_);                                \
        cp16(WS_ADDR(s_, lw_row, lw_colh), wp_);                                \
        cp16(WS_ADDR(s_, lw_row, lw_colh + 8), wp_ + 8);                        \
        asm volatile("cp.async.commit_group;" ::: "memory");                    \
    }

    // fetch first task; prime pipeline
    if (tid == 0) s_next = atomicAdd(&g_task[layer], 1);
    __syncthreads();
    int task = s_next;
    if (task >= NTASK) return;
    const __half* cur_x;
    const __half* cur_w;
    {
        TASK_PTRS(task, xg0, wp0);
        cur_x = xg0; cur_w = wp0;
        LOAD_STAGE(cur_x, cur_w, 0);
        LOAD_STAGE(cur_x, cur_w, 1);
        LOAD_STAGE(cur_x, cur_w, 2);
    }

    for (;;) {
        // claim next task (sync first: everyone has consumed s_next)
        __syncthreads();
        if (tid == 0) s_next = atomicAdd(&g_task[layer], 1);

        float acc[4][2][4];    // [gate][dt][c0..c3]
#pragma unroll
        for (int g = 0; g < 4; g++)
#pragma unroll
            for (int dt = 0; dt < 2; dt++)
#pragma unroll
                for (int j = 0; j < 4; j++) acc[g][dt][j] = 0.f;

#pragma unroll
        for (int kb = 0; kb < NKB; kb++) {
            int s = kb & 3;
            if (kb < NKB - 2) {
                WAITG(2);
            } else if (kb == NKB - 2) {
                WAITG(1);
            } else {
                WAITG(0);
            }
            __syncthreads();
            if (kb + 3 < NKB) LOAD_STAGE(cur_x, cur_w, kb + 3);

#pragma unroll
            for (int ks = 0; ks < 2; ks++) {
                int colh = ks * 16 + fcolh;
                uint32_t a[4];
                ldm_x4(a, XS_ADDR(s, m0 + frow, colh));
                uint32_t b[4][4];
#pragma unroll
                for (int g = 0; g < 4; g++)
                    ldm_x4(b[g], WS_ADDR(s, g * 32 + d0 + frow, colh));
#pragma unroll
                for (int g = 0; g < 4; g++)
#pragma unroll
                    for (int dt = 0; dt < 2; dt++)
                        mma_f16(acc[g][dt], a, b[g][dt], b[g][dt + 2]);
            }
        }

        // all warps done reading this task's stages
        __syncthreads();
        int next = s_next;
        if (next < NTASK) {
            TASK_PTRS(next, xgn, wpn);
            cur_x = xgn; cur_w = wpn;
            LOAD_STAGE(cur_x, cur_w, 0);
            LOAD_STAGE(cur_x, cur_w, 1);
            LOAD_STAGE(cur_x, cur_w, 2);
        }

        // ---- fused LSTM epilogue (gate order: i, o, f, cell) ----------------
        int m_base = (task >> 2) * 64;
        int d_base = (task & 3) * 32;
#pragma unroll
        for (int dt = 0; dt < 2; dt++) {
            int d = d_base + d0 + dt * 8 + tig * 2;
            float2 bi = *(const float2*)&bias[0 * HH + d];
            float2 bo = *(const float2*)&bias[1 * HH + d];
            float2 bf = *(const float2*)&bias[2 * HH + d];
            float2 bg = *(const float2*)&bias[3 * HH + d];
#pragma unroll
            for (int rr = 0; rr < 2; rr++) {
                int m = m_base + m0 + gid + rr * 8;
                size_t off = (size_t)m * HH + d;
                float2 cv = *(const float2*)&c_src[off];

                float i0 = sigf(acc[0][dt][rr * 2 + 0] + bi.x);
                float i1 = sigf(acc[0][dt][rr * 2 + 1] + bi.y);
                float o0 = sigf(acc[1][dt][rr * 2 + 0] + bo.x);
                float o1 = sigf(acc[1][dt][rr * 2 + 1] + bo.y);
                float f0 = sigf(acc[2][dt][rr * 2 + 0] + bf.x);
                float f1 = sigf(acc[2][dt][rr * 2 + 1] + bf.y);
                float g0 = tanhf(acc[3][dt][rr * 2 + 0] + bg.x);
                float g1 = tanhf(acc[3][dt][rr * 2 + 1] + bg.y);

                float cn0 = f0 * cv.x + i0 * g0;
                float cn1 = f1 * cv.y + i1 * g1;
                *(float2*)&c_dst[off] = make_float2(cn0, cn1);
                *(float2*)&h_dst[off] = make_float2(o0 * tanhf(cn0), o1 * tanhf(cn1));
            }
        }

        if (next >= NTASK) return;
        task = next;
    }
#undef XS_ADDR
#undef WS_ADDR
#undef LOAD_STAGE
#undef TASK_PTRS
}

// ---------------------------------------------------------------------------
extern "C" void kernel_launch(void* const* d_in, const int* in_sizes, int n_in,
                              void* d_out, int out_size) {
    const float* node_hidden = (const float*)d_in[0];
    const float* cell        = (const float*)d_in[1];
    const float* w_in        = (const float*)d_in[2];
    const float* w_out       = (const float*)d_in[3];
    const float* u_in        = (const float*)d_in[4];
    const float* u_out       = (const float*)d_in[5];
    const float* b           = (const float*)d_in[6];
    const float* in_msk      = (const float*)d_in[7];
    const float* out_msk     = (const float*)d_in[8];
    const int*   in_idx      = (const int*)d_in[9];
    const int*   out_idx     = (const int*)d_in[10];
    float* out = (float*)d_out;

    cudaFuncSetAttribute(gemm_lstm_mma,
                         cudaFuncAttributeMaxDynamicSharedMemorySize, SMEM_GEMM);

    prep_kernel<<<(NKB * 4 * HH * KB) / 256, 256>>>(w_in, w_out, u_in, u_out);

    // Layer 1
    agg_kernel<<<MM / 4, 256>>>(node_hidden, 1, in_idx, in_msk, out_idx, out_msk);
    gemm_lstm_mma<<<GRID_G, 256, SMEM_GEMM>>>(b, cell, out, 0);

    // Layer 2
    agg_kernel<<<MM / 4, 256>>>(nullptr, 0, in_idx, in_msk, out_idx, out_msk);
    gemm_lstm_mma<<<GRID_G, 256, SMEM_GEMM>>>(b, nullptr, out, 1);
}

// round 15
// speedup vs baseline: 1.3911x; 1.0672x over previous
#include <cuda_runtime.h>
#include <cuda_fp16.h>
#include <math.h>
#include <stdint.h>

// Problem constants (fixed by setup_inputs)
#define BB 8
#define NN 2000
#define HH 128
#define KK 32
#define MM (BB * NN)        // 16000 rows
#define KDIM 384            // concat [in_agg | out_agg | h]
#define KB 32               // k per pipeline stage (halfs)
#define NKB (KDIM / KB)     // 12 stages
#define ROWB 80             // padded smem row bytes (64 data + 16 pad)
#define XSTAGE_B (64 * ROWB)          // 5120 B per X stage (64 m-rows)
#define WSTAGE_B (128 * ROWB)         // 10240 B per W stage (4g x 32d rows)
#define SMEM_GEMM (4 * (XSTAGE_B + WSTAGE_B))   // 61440 B

#define NTILE 250           // 16000 / 64 exact
#define NTASK (NTILE * 4)   // 1000 (tile x dblock) per layer
#define GRID_G 444          // 3 CTAs/SM x 148 SMs

#define AGG_BLOCKS (MM / 4)            // 4000
#define PREP_BLOCKS 768                // 196608 / 256
#define AGG1_GRID (AGG_BLOCKS + PREP_BLOCKS)

// ---- scratch (device globals; no allocation allowed) ----------------------
__device__ __half g_Xh[MM * KDIM];             // X rows fp16, [m][k]
__device__ __half g_Wh[NKB * 4 * HH * KB];     // [kb][g][d][k] fp16
__device__ float  g_h[MM * HH];                // h after layer 1 (fp32)
__device__ float  g_c[MM * HH];                // cell scratch (fp32)
__device__ int    g_task[2];                   // work-steal counters per layer

// ---- helpers ---------------------------------------------------------------
__device__ __forceinline__ uint32_t smem_u32(const void* p) {
    uint32_t a;
    asm("{ .reg .u64 t; cvta.to.shared.u64 t, %1; cvt.u32.u64 %0, t; }" : "=r"(a) : "l"(p));
    return a;
}

__device__ __forceinline__ void cp16(uint32_t s, const void* g) {
    asm volatile("cp.async.cg.shared.global [%0], [%1], 16;" :: "r"(s), "l"(g));
}

__device__ __forceinline__ void ldm_x4(uint32_t* r, uint32_t addr) {
    asm volatile("ldmatrix.sync.aligned.m8n8.x4.shared.b16 {%0,%1,%2,%3}, [%4];"
                 : "=r"(r[0]), "=r"(r[1]), "=r"(r[2]), "=r"(r[3]) : "r"(addr));
}

__device__ __forceinline__ void mma_f16(float* c, const uint32_t* a,
                                        uint32_t b0, uint32_t b1) {
    asm volatile(
        "mma.sync.aligned.m16n8k16.row.col.f32.f16.f16.f32 "
        "{%0,%1,%2,%3}, {%4,%5,%6,%7}, {%8,%9}, {%0,%1,%2,%3};"
        : "+f"(c[0]), "+f"(c[1]), "+f"(c[2]), "+f"(c[3])
        : "r"(a[0]), "r"(a[1]), "r"(a[2]), "r"(a[3]), "r"(b0), "r"(b1));
}

// fast gate functions: __expf (2 ulp) based; overflow-safe
__device__ __forceinline__ float sigf(float x) {
    return __fdividef(1.f, 1.f + __expf(-x));
}
__device__ __forceinline__ float tanh_fast(float x) {
    float e = __expf(2.f * fabsf(x));              // >= 1; overflow -> inf
    float t = 1.f - __fdividef(2.f, e + 1.f);      // inf -> t = 1
    return copysignf(t, x);
}

#define WAITG(n) asm volatile("cp.async.wait_group %0;" :: "n"(n) : "memory")

// ---------------------------------------------------------------------------
// Aggregation (+ fused W-prep in extra blocks for layer 1).
// Blocks [0, 4000): TWO warps per node (one per edge set), 4 nodes/block,
//   8-deep explicit load batching for MLP.
// Blocks [4000, 4768) (layer-1 launch only): convert W to g_Wh fp16
//   ([kb][g][d][k]) and reset work-steal counters.
// ---------------------------------------------------------------------------
__global__ void __launch_bounds__(256, 4)
agg_kernel(const float* __restrict__ h_ext, int use_ext,
           const int*   __restrict__ in_idx,
           const float* __restrict__ in_msk,
           const int*   __restrict__ out_idx,
           const float* __restrict__ out_msk,
           const float* __restrict__ w_in,
           const float* __restrict__ w_out,
           const float* __restrict__ u_in,
           const float* __restrict__ u_out) {
    int tid = threadIdx.x;

    if (blockIdx.x >= AGG_BLOCKS) {
        // ---- prep branch -------------------------------------------------
        int pid = blockIdx.x - AGG_BLOCKS;
        if (pid == 0 && tid < 2) g_task[tid] = 0;
        int idx = pid * 256 + tid;      // [0, 196608)
        int k = idx & 31;
        int d = (idx >> 5) & 127;
        int g = (idx >> 12) & 3;
        int kb = idx >> 14;
        int kg = kb * KB + k;
        float v;
        if (kg < 128) {
            v = w_in[(g * 128 + kg) * 128 + d];
        } else if (kg < 256) {
            v = w_out[(g * 128 + (kg - 128)) * 128 + d];
        } else {
            int kk = kg - 256;
            v = u_in[(g * 128 + kk) * 128 + d] + u_out[(g * 128 + kk) * 128 + d];
        }
        g_Wh[idx] = __float2half_rn(v);
        return;
    }

    // ---- agg branch ------------------------------------------------------
    const float* h_src = use_ext ? h_ext : g_h;
    __shared__ int   s_idx[8][KK];
    __shared__ float s_msk[8][KK];

    int wid = tid >> 5;
    int lane = tid & 31;
    int es = wid & 1;                 // 0 = in, 1 = out
    int bn = blockIdx.x * 4 + (wid >> 1);

    {
        const int*   ip = es ? out_idx : in_idx;
        const float* mp = es ? out_msk : in_msk;
        s_idx[wid][lane] = ip[bn * KK + lane];
        s_msk[wid][lane] = mp[bn * KK + lane];
    }
    __syncwarp();

    int base_b = (bn / NN) * NN;
    const float4* h4 = (const float4*)h_src;

    float4 a = make_float4(0.f, 0.f, 0.f, 0.f);

#pragma unroll
    for (int kc = 0; kc < KK; kc += 8) {
        float4 v[8];
        float  m[8];
#pragma unroll
        for (int u = 0; u < 8; u++) {
            int j = s_idx[wid][kc + u];
            m[u] = s_msk[wid][kc + u];
            v[u] = h4[(size_t)(base_b + j) * 32 + lane];
        }
#pragma unroll
        for (int u = 0; u < 8; u++) {
            a.x += m[u] * v[u].x;
            a.y += m[u] * v[u].y;
            a.z += m[u] * v[u].z;
            a.w += m[u] * v[u].w;
        }
    }

    __half2* X2 = (__half2*)(g_Xh + (size_t)bn * KDIM);
    X2[es * 64 + lane * 2 + 0] = __floats2half2_rn(a.x, a.y);
    X2[es * 64 + lane * 2 + 1] = __floats2half2_rn(a.z, a.w);
    if (es == 0) {
        float4 hv = h4[(size_t)bn * 32 + lane];
        X2[2 * 64 + lane * 2 + 0] = __floats2half2_rn(hv.x, hv.y);
        X2[2 * 64 + lane * 2 + 1] = __floats2half2_rn(hv.z, hv.w);
    }
}

// ---------------------------------------------------------------------------
// fp16 mma.sync GEMM + fused LSTM. Persistent 444-CTA work-stealing kernel
// (3 CTAs/SM). Task = 64m x 32d x 4 gates; warp = 16m x 16d x 4g;
// 4-deep cp.async pipeline; next task's first stages issued before the
// current epilogue. Epilogue uses fast-math gates (__expf-based).
// ---------------------------------------------------------------------------
__global__ void __launch_bounds__(256, 3)
gemm_lstm_mma(const float* __restrict__ bias,
              const float* __restrict__ c_ext,
              float* __restrict__ h_final,
              int layer) {
    const float* c_src = layer ? g_c : c_ext;
    float* c_dst = g_c;
    float* h_dst = layer ? h_final : g_h;

    extern __shared__ char smem[];
    uint32_t xs_u = smem_u32(smem);
    uint32_t ws_u = xs_u + 4 * XSTAGE_B;
    __shared__ int s_next;

    int tid = threadIdx.x;
    int wid = tid >> 5;
    int lane = tid & 31;
    int m0 = (wid & 3) * 16;          // warp m-group (4 x 16 rows)
    int d0 = (wid >> 2) * 16;         // warp d-group (2 x 16 cols)

#define XS_ADDR(s, row, colh) (xs_u + (uint32_t)((s) * XSTAGE_B + (row) * ROWB + (colh) * 2))
#define WS_ADDR(s, row, colh) (ws_u + (uint32_t)((s) * WSTAGE_B + (row) * ROWB + (colh) * 2))

    // X loader: 64 rows x 64B; 4 threads/row x 16B
    int lx_row = tid >> 2;
    int lx_colh = (tid & 3) * 8;
    // W loader: 128 rows x 64B; 2 threads/row x 32B
    int lw_row = tid >> 1;
    int lw_colh = (tid & 1) * 16;
    int wg = lw_row >> 5;
    int wdl = lw_row & 31;

    int frow = (lane & 7) + ((lane >> 3) & 1) * 8;
    int fcolh = (lane >> 4) * 8;
    int gid = lane >> 2;
    int tig = lane & 3;

#define TASK_PTRS(task, xg, wp)                                                 \
    const __half* xg = g_Xh + (size_t)(((task) >> 2) * 64 + lx_row) * KDIM + lx_colh; \
    const __half* wp = g_Wh + ((size_t)(wg * HH) + ((task) & 3) * 32 + wdl) * KB + lw_colh;

#define LOAD_STAGE(xg, wp, kb)                                                  \
    {                                                                           \
        int s_ = (kb) & 3;                                                      \
        const __half* xp_ = (xg) + (size_t)(kb) * KB;                           \
        const __half* wp_ = (wp) + (size_t)(kb) * 4 * HH * KB;                  \
        cp16(XS_ADDR(s_, lx_row, lx_colh), xp_);                                \
        cp16(WS_ADDR(s_, lw_row, lw_colh), wp_);                                \
        cp16(WS_ADDR(s_, lw_row, lw_colh + 8), wp_ + 8);                        \
        asm volatile("cp.async.commit_group;" ::: "memory");                    \
    }

    // fetch first task; prime pipeline
    if (tid == 0) s_next = atomicAdd(&g_task[layer], 1);
    __syncthreads();
    int task = s_next;
    if (task >= NTASK) return;
    const __half* cur_x;
    const __half* cur_w;
    {
        TASK_PTRS(task, xg0, wp0);
        cur_x = xg0; cur_w = wp0;
        LOAD_STAGE(cur_x, cur_w, 0);
        LOAD_STAGE(cur_x, cur_w, 1);
        LOAD_STAGE(cur_x, cur_w, 2);
    }

    for (;;) {
        // claim next task (sync first: everyone has consumed s_next)
        __syncthreads();
        if (tid == 0) s_next = atomicAdd(&g_task[layer], 1);

        float acc[4][2][4];    // [gate][dt][c0..c3]
#pragma unroll
        for (int g = 0; g < 4; g++)
#pragma unroll
            for (int dt = 0; dt < 2; dt++)
#pragma unroll
                for (int j = 0; j < 4; j++) acc[g][dt][j] = 0.f;

#pragma unroll
        for (int kb = 0; kb < NKB; kb++) {
            int s = kb & 3;
            if (kb < NKB - 2) {
                WAITG(2);
            } else if (kb == NKB - 2) {
                WAITG(1);
            } else {
                WAITG(0);
            }
            __syncthreads();
            if (kb + 3 < NKB) LOAD_STAGE(cur_x, cur_w, kb + 3);

#pragma unroll
            for (int ks = 0; ks < 2; ks++) {
                int colh = ks * 16 + fcolh;
                uint32_t a[4];
                ldm_x4(a, XS_ADDR(s, m0 + frow, colh));
                uint32_t b[4][4];
#pragma unroll
                for (int g = 0; g < 4; g++)
                    ldm_x4(b[g], WS_ADDR(s, g * 32 + d0 + frow, colh));
#pragma unroll
                for (int g = 0; g < 4; g++)
#pragma unroll
                    for (int dt = 0; dt < 2; dt++)
                        mma_f16(acc[g][dt], a, b[g][dt], b[g][dt + 2]);
            }
        }

        // all warps done reading this task's stages
        __syncthreads();
        int next = s_next;
        if (next < NTASK) {
            TASK_PTRS(next, xgn, wpn);
            cur_x = xgn; cur_w = wpn;
            LOAD_STAGE(cur_x, cur_w, 0);
            LOAD_STAGE(cur_x, cur_w, 1);
            LOAD_STAGE(cur_x, cur_w, 2);
        }

        // ---- fused LSTM epilogue (gate order: i, o, f, cell) ----------------
        int m_base = (task >> 2) * 64;
        int d_base = (task & 3) * 32;
#pragma unroll
        for (int dt = 0; dt < 2; dt++) {
            int d = d_base + d0 + dt * 8 + tig * 2;
            float2 bi = *(const float2*)&bias[0 * HH + d];
            float2 bo = *(const float2*)&bias[1 * HH + d];
            float2 bf = *(const float2*)&bias[2 * HH + d];
            float2 bg = *(const float2*)&bias[3 * HH + d];
#pragma unroll
            for (int rr = 0; rr < 2; rr++) {
                int m = m_base + m0 + gid + rr * 8;
                size_t off = (size_t)m * HH + d;
                float2 cv = *(const float2*)&c_src[off];

                float i0 = sigf(acc[0][dt][rr * 2 + 0] + bi.x);
                float i1 = sigf(acc[0][dt][rr * 2 + 1] + bi.y);
                float o0 = sigf(acc[1][dt][rr * 2 + 0] + bo.x);
                float o1 = sigf(acc[1][dt][rr * 2 + 1] + bo.y);
                float f0 = sigf(acc[2][dt][rr * 2 + 0] + bf.x);
                float f1 = sigf(acc[2][dt][rr * 2 + 1] + bf.y);
                float g0 = tanh_fast(acc[3][dt][rr * 2 + 0] + bg.x);
                float g1 = tanh_fast(acc[3][dt][rr * 2 + 1] + bg.y);

                float cn0 = f0 * cv.x + i0 * g0;
                float cn1 = f1 * cv.y + i1 * g1;
                *(float2*)&c_dst[off] = make_float2(cn0, cn1);
                *(float2*)&h_dst[off] = make_float2(o0 * tanh_fast(cn0),
                                                   o1 * tanh_fast(cn1));
            }
        }

        if (next >= NTASK) return;
        task = next;
    }
#undef XS_ADDR
#undef WS_ADDR
#undef LOAD_STAGE
#undef TASK_PTRS
}

// ---------------------------------------------------------------------------
extern "C" void kernel_launch(void* const* d_in, const int* in_sizes, int n_in,
                              void* d_out, int out_size) {
    const float* node_hidden = (const float*)d_in[0];
    const float* cell        = (const float*)d_in[1];
    const float* w_in        = (const float*)d_in[2];
    const float* w_out       = (const float*)d_in[3];
    const float* u_in        = (const float*)d_in[4];
    const float* u_out       = (const float*)d_in[5];
    const float* b           = (const float*)d_in[6];
    const float* in_msk      = (const float*)d_in[7];
    const float* out_msk     = (const float*)d_in[8];
    const int*   in_idx      = (const int*)d_in[9];
    const int*   out_idx     = (const int*)d_in[10];
    float* out = (float*)d_out;

    cudaFuncSetAttribute(gemm_lstm_mma,
                         cudaFuncAttributeMaxDynamicSharedMemorySize, SMEM_GEMM);

    // Layer 1 (agg + fused W-prep + counter reset)
    agg_kernel<<<AGG1_GRID, 256>>>(node_hidden, 1, in_idx, in_msk,
                                   out_idx, out_msk, w_in, w_out, u_in, u_out);
    gemm_lstm_mma<<<GRID_G, 256, SMEM_GEMM>>>(b, cell, out, 0);

    // Layer 2
    agg_kernel<<<AGG_BLOCKS, 256>>>(nullptr, 0, in_idx, in_msk,
                                    out_idx, out_msk, w_in, w_out, u_in, u_out);
    gemm_lstm_mma<<<GRID_G, 256, SMEM_GEMM>>>(b, nullptr, out, 1);
}

// round 16
// speedup vs baseline: 1.4482x; 1.0411x over previous
#include <cuda_runtime.h>
#include <cuda_fp16.h>
#include <math.h>
#include <stdint.h>

// Problem constants (fixed by setup_inputs)
#define BB 8
#define NN 2000
#define HH 128
#define KK 32
#define MM (BB * NN)        // 16000 rows
#define KDIM 384            // concat [in_agg | out_agg | h]
#define KB 32               // k per pipeline stage (halfs)
#define NKB (KDIM / KB)     // 12 stages
#define ROWB 80             // padded smem row bytes (64 data + 16 pad)
#define XSTAGE_B (64 * ROWB)          // 5120 B per X stage (64 m-rows)
#define WSTAGE_B (128 * ROWB)         // 10240 B per W stage (4g x 32d rows)
#define SMEM_GEMM (4 * (XSTAGE_B + WSTAGE_B))   // 61440 B

#define NTILE 250           // 16000 / 64 exact
#define NTASK (NTILE * 4)   // 1000 (tile x dblock) per layer
#define GRID_G 444          // 3 CTAs/SM x 148 SMs

#define AGG_BLOCKS (MM / 4)            // 4000
#define PREP_BLOCKS 768                // 196608 / 256
#define AGG1_GRID (AGG_BLOCKS + PREP_BLOCKS)

// ---- scratch (device globals; no allocation allowed) ----------------------
__device__ __half g_Xh[MM * KDIM];             // X rows fp16, [m][k]
__device__ __half g_Wh[NKB * 4 * HH * KB];     // [kb][g][d][k] fp16
__device__ float  g_h[MM * HH];                // h after layer 1 (fp32)
__device__ float  g_c[MM * HH];                // cell scratch (fp32)
__device__ int    g_task[2];                   // work-steal counters per layer

// ---- helpers ---------------------------------------------------------------
__device__ __forceinline__ uint32_t smem_u32(const void* p) {
    uint32_t a;
    asm("{ .reg .u64 t; cvta.to.shared.u64 t, %1; cvt.u32.u64 %0, t; }" : "=r"(a) : "l"(p));
    return a;
}

__device__ __forceinline__ void cp16(uint32_t s, const void* g) {
    asm volatile("cp.async.cg.shared.global [%0], [%1], 16;" :: "r"(s), "l"(g));
}

__device__ __forceinline__ void ldm_x4(uint32_t* r, uint32_t addr) {
    asm volatile("ldmatrix.sync.aligned.m8n8.x4.shared.b16 {%0,%1,%2,%3}, [%4];"
                 : "=r"(r[0]), "=r"(r[1]), "=r"(r[2]), "=r"(r[3]) : "r"(addr));
}

__device__ __forceinline__ void mma_f16(float* c, const uint32_t* a,
                                        uint32_t b0, uint32_t b1) {
    asm volatile(
        "mma.sync.aligned.m16n8k16.row.col.f32.f16.f16.f32 "
        "{%0,%1,%2,%3}, {%4,%5,%6,%7}, {%8,%9}, {%0,%1,%2,%3};"
        : "+f"(c[0]), "+f"(c[1]), "+f"(c[2]), "+f"(c[3])
        : "r"(a[0]), "r"(a[1]), "r"(a[2]), "r"(a[3]), "r"(b0), "r"(b1));
}

// fast gate functions: __expf (2 ulp) based; overflow-safe
__device__ __forceinline__ float sigf(float x) {
    return __fdividef(1.f, 1.f + __expf(-x));
}
__device__ __forceinline__ float tanh_fast(float x) {
    float e = __expf(2.f * fabsf(x));              // >= 1; overflow -> inf
    float t = 1.f - __fdividef(2.f, e + 1.f);      // inf -> t = 1
    return copysignf(t, x);
}

#define WAITG(n) asm volatile("cp.async.wait_group %0;" :: "n"(n) : "memory")

// ---------------------------------------------------------------------------
// Aggregation (+ fused W-prep in extra blocks for layer 1).
// ---------------------------------------------------------------------------
__global__ void __launch_bounds__(256, 4)
agg_kernel(const float* __restrict__ h_ext, int use_ext,
           const int*   __restrict__ in_idx,
           const float* __restrict__ in_msk,
           const int*   __restrict__ out_idx,
           const float* __restrict__ out_msk,
           const float* __restrict__ w_in,
           const float* __restrict__ w_out,
           const float* __restrict__ u_in,
           const float* __restrict__ u_out) {
    int tid = threadIdx.x;

    if (blockIdx.x >= AGG_BLOCKS) {
        // ---- prep branch -------------------------------------------------
        int pid = blockIdx.x - AGG_BLOCKS;
        if (pid == 0 && tid < 2) g_task[tid] = 0;
        int idx = pid * 256 + tid;      // [0, 196608)
        int k = idx & 31;
        int d = (idx >> 5) & 127;
        int g = (idx >> 12) & 3;
        int kb = idx >> 14;
        int kg = kb * KB + k;
        float v;
        if (kg < 128) {
            v = w_in[(g * 128 + kg) * 128 + d];
        } else if (kg < 256) {
            v = w_out[(g * 128 + (kg - 128)) * 128 + d];
        } else {
            int kk = kg - 256;
            v = u_in[(g * 128 + kk) * 128 + d] + u_out[(g * 128 + kk) * 128 + d];
        }
        g_Wh[idx] = __float2half_rn(v);
        return;
    }

    // ---- agg branch ------------------------------------------------------
    const float* h_src = use_ext ? h_ext : g_h;
    __shared__ int   s_idx[8][KK];
    __shared__ float s_msk[8][KK];

    int wid = tid >> 5;
    int lane = tid & 31;
    int es = wid & 1;                 // 0 = in, 1 = out
    int bn = blockIdx.x * 4 + (wid >> 1);

    {
        const int*   ip = es ? out_idx : in_idx;
        const float* mp = es ? out_msk : in_msk;
        s_idx[wid][lane] = ip[bn * KK + lane];
        s_msk[wid][lane] = mp[bn * KK + lane];
    }
    __syncwarp();

    int base_b = (bn / NN) * NN;
    const float4* h4 = (const float4*)h_src;

    float4 a = make_float4(0.f, 0.f, 0.f, 0.f);

#pragma unroll
    for (int kc = 0; kc < KK; kc += 8) {
        float4 v[8];
        float  m[8];
#pragma unroll
        for (int u = 0; u < 8; u++) {
            int j = s_idx[wid][kc + u];
            m[u] = s_msk[wid][kc + u];
            v[u] = h4[(size_t)(base_b + j) * 32 + lane];
        }
#pragma unroll
        for (int u = 0; u < 8; u++) {
            a.x += m[u] * v[u].x;
            a.y += m[u] * v[u].y;
            a.z += m[u] * v[u].z;
            a.w += m[u] * v[u].w;
        }
    }

    __half2* X2 = (__half2*)(g_Xh + (size_t)bn * KDIM);
    X2[es * 64 + lane * 2 + 0] = __floats2half2_rn(a.x, a.y);
    X2[es * 64 + lane * 2 + 1] = __floats2half2_rn(a.z, a.w);
    if (es == 0) {
        float4 hv = h4[(size_t)bn * 32 + lane];
        X2[2 * 64 + lane * 2 + 0] = __floats2half2_rn(hv.x, hv.y);
        X2[2 * 64 + lane * 2 + 1] = __floats2half2_rn(hv.z, hv.w);
    }
}

// ---------------------------------------------------------------------------
// fp16 mma.sync GEMM + fused LSTM. Persistent 444-CTA work-stealing kernel
// (3 CTAs/SM). Task = 64m x 32d x 4 gates.
// NEW warp layout: 2 m-groups x 4 d-groups; warp = 32m x (8d x 4 gates).
//   A: 2 x ldm.x4 (rows m0..m0+31)
//   B: 2 x ldm.x4 with per-8-lane-group gate-strided row bases (4 gates x 8d)
// => 4 LDSM.x4 per k16 (was 5) and 16KB smem reads per CTA-k16 (was 20KB).
// ---------------------------------------------------------------------------
__global__ void __launch_bounds__(256, 3)
gemm_lstm_mma(const float* __restrict__ bias,
              const float* __restrict__ c_ext,
              float* __restrict__ h_final,
              int layer) {
    const float* c_src = layer ? g_c : c_ext;
    float* c_dst = g_c;
    float* h_dst = layer ? h_final : g_h;

    extern __shared__ char smem[];
    uint32_t xs_u = smem_u32(smem);
    uint32_t ws_u = xs_u + 4 * XSTAGE_B;
    __shared__ int s_next;

    int tid = threadIdx.x;
    int wid = tid >> 5;
    int lane = tid & 31;
    int m0 = (wid & 1) * 32;          // 2 m-groups of 32 rows
    int d0 = (wid >> 1) * 8;          // 4 d-groups of 8 cols

#define XS_ADDR(s, row, colh) (xs_u + (uint32_t)((s) * XSTAGE_B + (row) * ROWB + (colh) * 2))
#define WS_ADDR(s, row, colh) (ws_u + (uint32_t)((s) * WSTAGE_B + (row) * ROWB + (colh) * 2))

    // X loader: 64 rows x 64B; 4 threads/row x 16B
    int lx_row = tid >> 2;
    int lx_colh = (tid & 3) * 8;
    // W loader: 128 rows x 64B; 2 threads/row x 32B
    int lw_row = tid >> 1;
    int lw_colh = (tid & 1) * 16;
    int wg = lw_row >> 5;
    int wdl = lw_row & 31;

    // A ldmatrix lane mapping (matrices: r0-7/klo, r8-15/klo, r0-7/khi, r8-15/khi)
    int frow = (lane & 7) + ((lane >> 3) & 1) * 8;
    int fcolh = (lane >> 4) * 8;
    // B ldmatrix lane mapping: group = lane>>3 -> (gate pair, k-half)
    int b_gate_off = ((lane >> 4) & 1) * 32;     // matrices 0,1 -> gate+0; 2,3 -> gate+1
    int b_khalf = ((lane >> 3) & 1) * 8;         // matrices 0,2 -> klo; 1,3 -> khi
    int brow = lane & 7;
    int gid = lane >> 2;
    int tig = lane & 3;

#define TASK_PTRS(task, xg, wp)                                                 \
    const __half* xg = g_Xh + (size_t)(((task) >> 2) * 64 + lx_row) * KDIM + lx_colh; \
    const __half* wp = g_Wh + ((size_t)(wg * HH) + ((task) & 3) * 32 + wdl) * KB + lw_colh;

#define LOAD_STAGE(xg, wp, kb)                                                  \
    {                                                                           \
        int s_ = (kb) & 3;                                                      \
        const __half* xp_ = (xg) + (size_t)(kb) * KB;                           \
        const __half* wp_ = (wp) + (size_t)(kb) * 4 * HH * KB;                  \
        cp16(XS_ADDR(s_, lx_row, lx_colh), xp_);                                \
        cp16(WS_ADDR(s_, lw_row, lw_colh), wp_);                                \
        cp16(WS_ADDR(s_, lw_row, lw_colh + 8), wp_ + 8);                        \
        asm volatile("cp.async.commit_group;" ::: "memory");                    \
    }

    // fetch first task; prime pipeline
    if (tid == 0) s_next = atomicAdd(&g_task[layer], 1);
    __syncthreads();
    int task = s_next;
    if (task >= NTASK) return;
    const __half* cur_x;
    const __half* cur_w;
    {
        TASK_PTRS(task, xg0, wp0);
        cur_x = xg0; cur_w = wp0;
        LOAD_STAGE(cur_x, cur_w, 0);
        LOAD_STAGE(cur_x, cur_w, 1);
        LOAD_STAGE(cur_x, cur_w, 2);
    }

    for (;;) {
        // claim next task (sync first: everyone has consumed s_next)
        __syncthreads();
        if (tid == 0) s_next = atomicAdd(&g_task[layer], 1);

        float acc[4][2][4];    // [gate][mt][c0..c3]
#pragma unroll
        for (int g = 0; g < 4; g++)
#pragma unroll
            for (int mt = 0; mt < 2; mt++)
#pragma unroll
                for (int j = 0; j < 4; j++) acc[g][mt][j] = 0.f;

#pragma unroll
        for (int kb = 0; kb < NKB; kb++) {
            int s = kb & 3;
            if (kb < NKB - 2) {
                WAITG(2);
            } else if (kb == NKB - 2) {
                WAITG(1);
            } else {
                WAITG(0);
            }
            __syncthreads();
            if (kb + 3 < NKB) LOAD_STAGE(cur_x, cur_w, kb + 3);

#pragma unroll
            for (int ks = 0; ks < 2; ks++) {
                int colh = ks * 16;
                uint32_t a[2][4];
                ldm_x4(a[0], XS_ADDR(s, m0 + frow, colh + fcolh));
                ldm_x4(a[1], XS_ADDR(s, m0 + 16 + frow, colh + fcolh));
                // B: gates 0,1 then gates 2,3; regs b[2g], b[2g+1] = klo, khi
                uint32_t b[8];
                ldm_x4(b,     WS_ADDR(s, b_gate_off + d0 + brow,      colh + b_khalf));
                ldm_x4(b + 4, WS_ADDR(s, 64 + b_gate_off + d0 + brow, colh + b_khalf));
#pragma unroll
                for (int g = 0; g < 4; g++)
#pragma unroll
                    for (int mt = 0; mt < 2; mt++)
                        mma_f16(acc[g][mt], a[mt], b[g * 2], b[g * 2 + 1]);
            }
        }

        // all warps done reading this task's stages
        __syncthreads();
        int next = s_next;
        if (next < NTASK) {
            TASK_PTRS(next, xgn, wpn);
            cur_x = xgn; cur_w = wpn;
            LOAD_STAGE(cur_x, cur_w, 0);
            LOAD_STAGE(cur_x, cur_w, 1);
            LOAD_STAGE(cur_x, cur_w, 2);
        }

        // ---- fused LSTM epilogue (gate order: i, o, f, cell) ----------------
        int m_base = (task >> 2) * 64;
        int d_base = (task & 3) * 32;
        {
            int d = d_base + d0 + tig * 2;
            float2 bi = *(const float2*)&bias[0 * HH + d];
            float2 bo = *(const float2*)&bias[1 * HH + d];
            float2 bf = *(const float2*)&bias[2 * HH + d];
            float2 bg = *(const float2*)&bias[3 * HH + d];
#pragma unroll
            for (int mt = 0; mt < 2; mt++) {
#pragma unroll
                for (int rr = 0; rr < 2; rr++) {
                    int m = m_base + m0 + mt * 16 + gid + rr * 8;
                    size_t off = (size_t)m * HH + d;
                    float2 cv = *(const float2*)&c_src[off];

                    float i0 = sigf(acc[0][mt][rr * 2 + 0] + bi.x);
                    float i1 = sigf(acc[0][mt][rr * 2 + 1] + bi.y);
                    float o0 = sigf(acc[1][mt][rr * 2 + 0] + bo.x);
                    float o1 = sigf(acc[1][mt][rr * 2 + 1] + bo.y);
                    float f0 = sigf(acc[2][mt][rr * 2 + 0] + bf.x);
                    float f1 = sigf(acc[2][mt][rr * 2 + 1] + bf.y);
                    float g0 = tanh_fast(acc[3][mt][rr * 2 + 0] + bg.x);
                    float g1 = tanh_fast(acc[3][mt][rr * 2 + 1] + bg.y);

                    float cn0 = f0 * cv.x + i0 * g0;
                    float cn1 = f1 * cv.y + i1 * g1;
                    *(float2*)&c_dst[off] = make_float2(cn0, cn1);
                    *(float2*)&h_dst[off] = make_float2(o0 * tanh_fast(cn0),
                                                        o1 * tanh_fast(cn1));
                }
            }
        }

        if (next >= NTASK) return;
        task = next;
    }
#undef XS_ADDR
#undef WS_ADDR
#undef LOAD_STAGE
#undef TASK_PTRS
}

// ---------------------------------------------------------------------------
extern "C" void kernel_launch(void* const* d_in, const int* in_sizes, int n_in,
                              void* d_out, int out_size) {
    const float* node_hidden = (const float*)d_in[0];
    const float* cell        = (const float*)d_in[1];
    const float* w_in        = (const float*)d_in[2];
    const float* w_out       = (const float*)d_in[3];
    const float* u_in        = (const float*)d_in[4];
    const float* u_out       = (const float*)d_in[5];
    const float* b           = (const float*)d_in[6];
    const float* in_msk      = (const float*)d_in[7];
    const float* out_msk     = (const float*)d_in[8];
    const int*   in_idx      = (const int*)d_in[9];
    const int*   out_idx     = (const int*)d_in[10];
    float* out = (float*)d_out;

    cudaFuncSetAttribute(gemm_lstm_mma,
                         cudaFuncAttributeMaxDynamicSharedMemorySize, SMEM_GEMM);

    // Layer 1 (agg + fused W-prep + counter reset)
    agg_kernel<<<AGG1_GRID, 256>>>(node_hidden, 1, in_idx, in_msk,
                                   out_idx, out_msk, w_in, w_out, u_in, u_out);
    gemm_lstm_mma<<<GRID_G, 256, SMEM_GEMM>>>(b, cell, out, 0);

    // Layer 2
    agg_kernel<<<AGG_BLOCKS, 256>>>(nullptr, 0, in_idx, in_msk,
                                    out_idx, out_msk, w_in, w_out, u_in, u_out);
    gemm_lstm_mma<<<GRID_G, 256, SMEM_GEMM>>>(b, nullptr, out, 1);
}